// round 8
// baseline (speedup 1.0000x reference)
#include <cuda_runtime.h>
#include <cuda_fp16.h>
#include <cstdint>

#define LATENT   128
#define HIDDEN   2048
#define NPARTS   128
#define KCOLS    2048
#define OMEGA_D  1152
#define TRANZ_D  384
#define TRANSF_D 1536

// ---------------------------------------------------------------------------
// Scratch (__device__ globals; allocation-guard-safe)
// ---------------------------------------------------------------------------
#define W_TOTAL (2048*128 + 2048*2048 + 2048*2048 + 1152*2048 + \
                 2048*128 + 2048*2048 + 2048*2048 + 384*2048)

__device__ __half g_w_hi[W_TOTAL];
__device__ __half g_w_lo[W_TOTAL];
__device__ __half g_act[2][HIDDEN * KCOLS];     // plain fp16 activations
__device__ __half g_xt[KCOLS * LATENT];
__device__ float g_omega_part[2 * (size_t)KCOLS * OMEGA_D];
__device__ float g_trans_part[3 * (size_t)KCOLS * TRANZ_D];

// ---------------------------------------------------------------------------
// PTX helpers (base ISA: ldmatrix / mma.sync / cp.async)
// ---------------------------------------------------------------------------
__device__ __forceinline__ uint32_t smem_u32(const void* p) {
    uint32_t a;
    asm("{ .reg .u64 t; cvta.to.shared.u64 t, %1; cvt.u32.u64 %0, t; }" : "=r"(a) : "l"(p));
    return a;
}
__device__ __forceinline__ void cp16(uint32_t s, const void* g) {
    asm volatile("cp.async.cg.shared.global [%0], [%1], 16;" :: "r"(s), "l"(g) : "memory");
}
#define CP_COMMIT() asm volatile("cp.async.commit_group;" ::: "memory")

__device__ __forceinline__ void ldsm_x4(uint32_t addr, uint32_t* r) {
    asm volatile("ldmatrix.sync.aligned.m8n8.x4.shared.b16 {%0,%1,%2,%3}, [%4];"
                 : "=r"(r[0]), "=r"(r[1]), "=r"(r[2]), "=r"(r[3]) : "r"(addr));
}
// f32-accumulate MMA (hi term)
__device__ __forceinline__ void mma_f16(float* c, const uint32_t* a,
                                        uint32_t b0, uint32_t b1) {
    asm volatile(
        "mma.sync.aligned.m16n8k16.row.col.f32.f16.f16.f32 "
        "{%0,%1,%2,%3}, {%4,%5,%6,%7}, {%8,%9}, {%0,%1,%2,%3};"
        : "+f"(c[0]), "+f"(c[1]), "+f"(c[2]), "+f"(c[3])
        : "r"(a[0]), "r"(a[1]), "r"(a[2]), "r"(a[3]), "r"(b0), "r"(b1));
}
// f16-accumulate MMA (lo term; c = 2x packed f16x2)
__device__ __forceinline__ void mma_f16acc(uint32_t* c, const uint32_t* a,
                                           uint32_t b0, uint32_t b1) {
    asm volatile(
        "mma.sync.aligned.m16n8k16.row.col.f16.f16.f16.f16 "
        "{%0,%1}, {%2,%3,%4,%5}, {%6,%7}, {%0,%1};"
        : "+r"(c[0]), "+r"(c[1])
        : "r"(a[0]), "r"(a[1]), "r"(a[2]), "r"(a[3]), "r"(b0), "r"(b1));
}

// ---------------------------------------------------------------------------
// Fused weight split: all 8 weights -> (hi, lo) fp16, one launch.
// ---------------------------------------------------------------------------
__global__ __launch_bounds__(256) void split_w_kernel(
    const float* __restrict__ w0, const float* __restrict__ w1,
    const float* __restrict__ w2, const float* __restrict__ w3,
    const float* __restrict__ w4, const float* __restrict__ w5,
    const float* __restrict__ w6, const float* __restrict__ w7,
    __half* __restrict__ hi, __half* __restrict__ lo)
{
    const int cum[8] = {65536, 1114112, 2162688, 2752512,
                        2818048, 3866624, 4915200, 5111808};
    int idx = blockIdx.x * 256 + threadIdx.x;
    if (idx >= 5111808) return;
    const float* srcs[8] = {w0, w1, w2, w3, w4, w5, w6, w7};
    int s = 0;
#pragma unroll
    for (int i = 0; i < 7; i++) s += (idx >= cum[i]);
    int local = idx - (s ? cum[s - 1] : 0);
    float4 v = ((const float4*)srcs[s])[local];
    float f[4] = {v.x, v.y, v.z, v.w};
    __align__(8) __half h[4], l[4];
#pragma unroll
    for (int j = 0; j < 4; j++) {
        h[j] = __float2half(f[j]);
        l[j] = __float2half(f[j] - __half2float(h[j]));
    }
    ((uint2*)hi)[idx] = *(const uint2*)h;
    ((uint2*)lo)[idx] = *(const uint2*)l;
}

// x (LATENT, KCOLS) -> xt (KCOLS, LATENT), plain fp16
__global__ __launch_bounds__(256) void split_xT_kernel(
    const float* __restrict__ x, __half* __restrict__ out)
{
    int i = blockIdx.x * 256 + threadIdx.x;  // i = n*LATENT + f
    int f = i & (LATENT - 1);
    int n = i >> 7;
    out[i] = __float2half(x[(size_t)f * KCOLS + n]);
}

// ---------------------------------------------------------------------------
// HMMA 2-MMA split GEMM:  C = (Ah + Al) @ B^T.
// Hi term: f32-acc MMA. Lo term: f16-acc MMA, folded into f32 every kt.
// Output TRANSPOSED [n][M]. mode 0: relu + fp16; mode 1: fp32 raw.
// CTA 128x128x32, 256 threads, warp tile 64x32, 3-stage cp.async, 2 CTAs/SM.
// ---------------------------------------------------------------------------
#define BM 128
#define BN 128
#define BK 32
#define GT 256
#define PITCH 80
#define TILE_B (128 * PITCH)      // 10240
#define OFF_AH 0
#define OFF_AL TILE_B
#define OFF_B  (2 * TILE_B)
#define STAGE_B (3 * TILE_B)      // 30720
#define NSTAGE 3
#define GEMM_SMEM (NSTAGE * STAGE_B)   // 92160

__device__ __forceinline__ void load_stage(
    const __half* __restrict__ Ah, const __half* __restrict__ Al,
    const __half* __restrict__ B, int Kd, int m0, int n0, int kk,
    uint32_t stage_sb, int tid)
{
#pragma unroll
    for (int i = 0; i < 6; i++) {
        const int c = tid + i * 256;
        const int row = c >> 2;
        const int cb = (c & 3) * 16;
        const __half* gsrc;
        int grow;
        uint32_t soff;
        if (row < 128)      { gsrc = Ah; grow = m0 + row;       soff = OFF_AH + row * PITCH; }
        else if (row < 256) { gsrc = Al; grow = m0 + row - 128; soff = OFF_AL + (row - 128) * PITCH; }
        else                { gsrc = B;  grow = n0 + row - 256; soff = OFF_B  + (row - 256) * PITCH; }
        cp16(stage_sb + soff + cb,
             (const char*)(gsrc + (size_t)grow * Kd + kk) + cb);
    }
}

__global__ __launch_bounds__(GT, 2) void gemm_hmma_kernel(
    const __half* __restrict__ A_hi, const __half* __restrict__ A_lo,
    const __half* __restrict__ B, __half* __restrict__ out_h,
    float* __restrict__ out_f32, int M, int Kd, int mode,
    int ktps, size_t out_stride)
{
    extern __shared__ __align__(128) char smem[];
    const uint32_t sb = smem_u32(smem);
    const int tid = threadIdx.x;
    const int lane = tid & 31;
    const int wid = tid >> 5;                 // 0..7
    const int warp_m0 = (wid & 1) * 64;
    const int warp_n0 = (wid >> 1) * 32;
    const int m0 = blockIdx.y * BM;
    const int n0 = blockIdx.x * BN;
    const int KT = Kd / BK;
    const int ktb = blockIdx.z * ktps;
    const int L = min(KT - ktb, ktps);
    out_f32 += (size_t)blockIdx.z * out_stride;

    const int a_row = (lane & 7) + ((lane >> 3) & 1) * 8;
    const int a_kb  = (lane >> 4) * 16;
    const int b_row = (lane & 7) + (lane >> 4) * 8;
    const int b_kb  = ((lane >> 3) & 1) * 16;

    float acc[4][4][4];
#pragma unroll
    for (int mt = 0; mt < 4; mt++)
#pragma unroll
        for (int nt = 0; nt < 4; nt++)
#pragma unroll
            for (int i = 0; i < 4; i++) acc[mt][nt][i] = 0.0f;

    load_stage(A_hi, A_lo, B, Kd, m0, n0, ktb * BK, sb, tid);
    CP_COMMIT();
    load_stage(A_hi, A_lo, B, Kd, m0, n0, (ktb + 1) * BK, sb + STAGE_B, tid);
    CP_COMMIT();

    for (int kt = 0; kt < L; kt++) {
        asm volatile("cp.async.wait_group 1;" ::: "memory");
        __syncthreads();

        if (kt + 2 < L) {
            load_stage(A_hi, A_lo, B, Kd, m0, n0, (ktb + kt + 2) * BK,
                       sb + ((kt + 2) % NSTAGE) * STAGE_B, tid);
        }
        CP_COMMIT();

        const uint32_t st = sb + (kt % NSTAGE) * STAGE_B;

        // per-kt f16 accumulators for the lo term
        uint32_t accl[4][4][2];
#pragma unroll
        for (int mt = 0; mt < 4; mt++)
#pragma unroll
            for (int nt = 0; nt < 4; nt++) {
                accl[mt][nt][0] = 0u;
                accl[mt][nt][1] = 0u;
            }

#pragma unroll
        for (int ks = 0; ks < 2; ks++) {
            const int kb = ks * 32;
            uint32_t bq[2][4];
#pragma unroll
            for (int g = 0; g < 2; g++) {
                uint32_t rb = st + OFF_B + (warp_n0 + g * 16 + b_row) * PITCH + kb + b_kb;
                ldsm_x4(rb, bq[g]);
            }
#pragma unroll
            for (int mt = 0; mt < 4; mt++) {
                uint32_t ah[4], al[4];
                uint32_t ra = st + (warp_m0 + mt * 16 + a_row) * PITCH + kb + a_kb;
                ldsm_x4(ra + OFF_AH, ah);
                ldsm_x4(ra + OFF_AL, al);
#pragma unroll
                for (int nt = 0; nt < 4; nt++) {
                    const int g = nt >> 1, p = (nt & 1) * 2;
                    mma_f16(acc[mt][nt], ah, bq[g][p], bq[g][p + 1]);
                    mma_f16acc(accl[mt][nt], al, bq[g][p], bq[g][p + 1]);
                }
            }
        }

        // fold lo (f16) into f32 accumulators
#pragma unroll
        for (int mt = 0; mt < 4; mt++)
#pragma unroll
            for (int nt = 0; nt < 4; nt++) {
                float2 lo0 = __half22float2(*(const __half2*)&accl[mt][nt][0]);
                float2 lo1 = __half22float2(*(const __half2*)&accl[mt][nt][1]);
                acc[mt][nt][0] += lo0.x;
                acc[mt][nt][1] += lo0.y;
                acc[mt][nt][2] += lo1.x;
                acc[mt][nt][3] += lo1.y;
            }
    }

    // ---------------- epilogue: transpose via SMEM (128 x 132 fp32) --------
    __syncthreads();
    float* sC = (float*)smem;
    const int crow = lane >> 2, ccol = (lane & 3) * 2;
#pragma unroll
    for (int mt = 0; mt < 4; mt++)
#pragma unroll
        for (int nt = 0; nt < 4; nt++) {
            const int m_ = warp_m0 + mt * 16 + crow;
            const int n_ = warp_n0 + nt * 8 + ccol;
            const float* c = acc[mt][nt];
            sC[(size_t)n_ * 132 + m_]           = c[0];
            sC[(size_t)(n_ + 1) * 132 + m_]     = c[1];
            sC[(size_t)n_ * 132 + m_ + 8]       = c[2];
            sC[(size_t)(n_ + 1) * 132 + m_ + 8] = c[3];
        }
    __syncthreads();

    const int r  = tid >> 1;          // n row 0..127
    const int mh = (tid & 1) * 64;    // m half
    const size_t base = (size_t)(n0 + r) * M + m0 + mh;
    const float* srow = &sC[(size_t)r * 132 + mh];
    if (mode == 0) {
#pragma unroll
        for (int j0 = 0; j0 < 64; j0 += 8) {
            __align__(16) __half h8[8];
#pragma unroll
            for (int j = 0; j < 8; j++)
                h8[j] = __float2half(fmaxf(srow[j0 + j], 0.0f));
            *(uint4*)(out_h + base + j0) = *(const uint4*)h8;
        }
    } else {
#pragma unroll
        for (int j0 = 0; j0 < 64; j0 += 4) {
            float4 v;
            v.x = srow[j0 + 0]; v.y = srow[j0 + 1];
            v.z = srow[j0 + 2]; v.w = srow[j0 + 3];
            *(float4*)(out_f32 + base + j0) = v;
        }
    }
}

// ---------------------------------------------------------------------------
// expm (3x3) + output assembly; sums split-K partials (2 omega, 3 trans).
// ---------------------------------------------------------------------------
__device__ __forceinline__ void mm3(const float* X, const float* Y, float* Z) {
#pragma unroll
    for (int r = 0; r < 3; r++)
#pragma unroll
        for (int c = 0; c < 3; c++)
            Z[3 * r + c] = fmaf(X[3 * r + 0], Y[c],
                           fmaf(X[3 * r + 1], Y[3 + c], X[3 * r + 2] * Y[6 + c]));
}

__device__ void expm3(const float* A, float* E) {
    float n0 = fabsf(A[0]) + fabsf(A[1]) + fabsf(A[2]);
    float n1 = fabsf(A[3]) + fabsf(A[4]) + fabsf(A[5]);
    float n2 = fabsf(A[6]) + fabsf(A[7]) + fabsf(A[8]);
    float nrm = fmaxf(n0, fmaxf(n1, n2));
    int s = 0;
    if (nrm > 0.25f) {
        s = (int)ceilf(log2f(nrm * 4.0f));
        if (s < 0) s = 0;
    }
    float sc = exp2f((float)(-s));
    float B[9], T[9];
#pragma unroll
    for (int i = 0; i < 9; i++) B[i] = A[i] * sc;
#pragma unroll
    for (int i = 0; i < 9; i++) {
        T[i] = B[i];
        E[i] = ((i == 0) | (i == 4) | (i == 8)) ? 1.0f + B[i] : B[i];
    }
#pragma unroll
    for (int j = 2; j <= 10; j++) {
        float Tn[9];
        mm3(T, B, Tn);
        float inv = 1.0f / (float)j;
#pragma unroll
        for (int i = 0; i < 9; i++) { Tn[i] *= inv; E[i] += Tn[i]; T[i] = Tn[i]; }
    }
    for (int q = 0; q < s; q++) {
        float S[9];
        mm3(E, E, S);
#pragma unroll
        for (int i = 0; i < 9; i++) E[i] = S[i];
    }
}

__global__ __launch_bounds__(256) void expm_assemble_kernel(
    const float* __restrict__ omega_part, // 2 x (K, 9n)
    const float* __restrict__ trans_part, // 3 x (K, 3n)
    float* __restrict__ omega_out,        // (9n, K)
    float* __restrict__ transf,           // (12n, K)
    float* __restrict__ rot,              // (9n, K)
    float* __restrict__ trans_out)        // (3n, K)
{
    const int n = blockIdx.x * 256 + threadIdx.x;
    const int p = blockIdx.y;
    const size_t SO = (size_t)KCOLS * OMEGA_D;
    const size_t ST = (size_t)KCOLS * TRANZ_D;

    float Am[9];
    const size_t obase = (size_t)n * OMEGA_D + 9 * p;
#pragma unroll
    for (int j = 0; j < 9; j++)
        Am[j] = __ldg(omega_part + obase + j) + __ldg(omega_part + SO + obase + j);

    float E[9];
    expm3(Am, E);

#pragma unroll
    for (int j = 0; j < 9; j++) {
        omega_out[(size_t)(9 * p + j) * KCOLS + n] = Am[j];
        rot[(size_t)(9 * p + j) * KCOLS + n]       = E[j];
        transf[(size_t)(12 * p + j) * KCOLS + n]   = E[j];
    }
    const size_t tbase = (size_t)n * TRANZ_D + 3 * p;
#pragma unroll
    for (int c = 0; c < 3; c++) {
        float tv = __ldg(trans_part + tbase + c)
                 + __ldg(trans_part + ST + tbase + c)
                 + __ldg(trans_part + 2 * ST + tbase + c);
        trans_out[(size_t)(3 * p + c) * KCOLS + n]   = tv;
        transf[(size_t)(12 * p + 9 + c) * KCOLS + n] = tv;
    }
}

// ---------------------------------------------------------------------------
// kernel_launch
// ---------------------------------------------------------------------------
extern "C" void kernel_launch(void* const* d_in, const int* in_sizes, int n_in,
                              void* d_out, int out_size)
{
    const float* x = (const float*)d_in[0];
    const float* W[8];
    for (int i = 0; i < 8; i++) W[i] = (const float*)d_in[1 + i];

    const int wsz[8] = {2048 * 128, 2048 * 2048, 2048 * 2048, 1152 * 2048,
                        2048 * 128, 2048 * 2048, 2048 * 2048, 384 * 2048};
    size_t woff[8];
    size_t acc = 0;
    for (int i = 0; i < 8; i++) { woff[i] = acc; acc += wsz[i]; }

    float* out    = (float*)d_out;
    float* omega  = out;
    float* transf = omega  + (size_t)OMEGA_D  * KCOLS;
    float* rot    = transf + (size_t)TRANSF_D * KCOLS;
    float* trans  = rot    + (size_t)OMEGA_D  * KCOLS;

    __half *w_hi, *w_lo, *xt, *a0, *a1;
    float *omega_part, *trans_part;
    cudaGetSymbolAddress((void**)&w_hi, g_w_hi);
    cudaGetSymbolAddress((void**)&w_lo, g_w_lo);
    cudaGetSymbolAddress((void**)&xt, g_xt);
    {
        __half* p;
        cudaGetSymbolAddress((void**)&p, g_act);
        a0 = p; a1 = p + (size_t)HIDDEN * KCOLS;
    }
    cudaGetSymbolAddress((void**)&omega_part, g_omega_part);
    cudaGetSymbolAddress((void**)&trans_part, g_trans_part);

    cudaFuncSetAttribute(gemm_hmma_kernel,
                         cudaFuncAttributeMaxDynamicSharedMemorySize, GEMM_SMEM);

    // 1) fused weight split + xT convert
    split_w_kernel<<<(5111808 + 255) / 256, 256>>>(
        W[0], W[1], W[2], W[3], W[4], W[5], W[6], W[7], w_hi, w_lo);
    split_xT_kernel<<<(KCOLS * LATENT) / 256, 256>>>(x, xt);

    // 2) GEMM chains
    auto gemm = [&](int wi, const __half* b, __half* oh, float* of,
                    int M, int Kd, int mode, int zsplits, size_t ostride) {
        int KT = Kd / BK;
        int ktps = (KT + zsplits - 1) / zsplits;
        dim3 grid(KCOLS / BN, M / BM, zsplits);
        gemm_hmma_kernel<<<grid, GT, GEMM_SMEM>>>(
            w_hi + woff[wi], w_lo + woff[wi], b, oh, of,
            M, Kd, mode, ktps, ostride);
    };

    // omega branch (layer3 split-K x2)
    gemm(0, xt, a0, nullptr, HIDDEN,  LATENT, 0, 1, 0);
    gemm(1, a0, a1, nullptr, HIDDEN,  HIDDEN, 0, 1, 0);
    gemm(2, a1, a0, nullptr, HIDDEN,  HIDDEN, 0, 1, 0);
    gemm(3, a0, nullptr, omega_part, OMEGA_D, HIDDEN, 1, 2,
         (size_t)KCOLS * OMEGA_D);
    // translation branch (layer7 split-K x3)
    gemm(4, xt, a0, nullptr, HIDDEN,  LATENT, 0, 1, 0);
    gemm(5, a0, a1, nullptr, HIDDEN,  HIDDEN, 0, 1, 0);
    gemm(6, a1, a0, nullptr, HIDDEN,  HIDDEN, 0, 1, 0);
    gemm(7, a0, nullptr, trans_part, TRANZ_D, HIDDEN, 1, 3,
         (size_t)KCOLS * TRANZ_D);

    // 3) expm + assembly
    dim3 ge(KCOLS / 256, NPARTS);
    expm_assemble_kernel<<<ge, 256>>>(omega_part, trans_part, omega, transf,
                                      rot, trans);
}

// round 9
// speedup vs baseline: 1.1508x; 1.1508x over previous
#include <cuda_runtime.h>
#include <cuda_fp16.h>
#include <cstdint>

#define LATENT   128
#define HIDDEN   2048
#define NPARTS   128
#define KCOLS    2048
#define OMEGA_D  1152
#define TRANZ_D  384
#define TRANSF_D 1536

// ---------------------------------------------------------------------------
// Scratch (__device__ globals; allocation-guard-safe)
// Weight order in scratch: w0, w4, w1, w2, w3, w5, w6, w7  (w0/w4 adjacent so
// the merged first layer sees one contiguous M=4096 weight block).
// ---------------------------------------------------------------------------
#define W_TOTAL (2048*128 + 2048*128 + 2048*2048 + 2048*2048 + 1152*2048 + \
                 2048*2048 + 2048*2048 + 384*2048)

__device__ __half g_w_hi[W_TOTAL];
__device__ __half g_w_lo[W_TOTAL];
__device__ __half g_act0[(size_t)KCOLS * 4096];   // merged layer0+4 output
__device__ __half g_act1[(size_t)KCOLS * HIDDEN];
__device__ __half g_act2[(size_t)KCOLS * HIDDEN];
__device__ __half g_xt[KCOLS * LATENT];
__device__ float g_omega_part[2 * (size_t)KCOLS * OMEGA_D];
__device__ float g_trans_part[3 * (size_t)KCOLS * TRANZ_D];

// ---------------------------------------------------------------------------
// PTX helpers (base ISA: ldmatrix / mma.sync / cp.async)
// ---------------------------------------------------------------------------
__device__ __forceinline__ uint32_t smem_u32(const void* p) {
    uint32_t a;
    asm("{ .reg .u64 t; cvta.to.shared.u64 t, %1; cvt.u32.u64 %0, t; }" : "=r"(a) : "l"(p));
    return a;
}
__device__ __forceinline__ void cp16(uint32_t s, const void* g) {
    asm volatile("cp.async.cg.shared.global [%0], [%1], 16;" :: "r"(s), "l"(g) : "memory");
}
#define CP_COMMIT() asm volatile("cp.async.commit_group;" ::: "memory")

__device__ __forceinline__ void ldsm_x4(uint32_t addr, uint32_t* r) {
    asm volatile("ldmatrix.sync.aligned.m8n8.x4.shared.b16 {%0,%1,%2,%3}, [%4];"
                 : "=r"(r[0]), "=r"(r[1]), "=r"(r[2]), "=r"(r[3]) : "r"(addr));
}
__device__ __forceinline__ void mma_f16(float* c, const uint32_t* a,
                                        uint32_t b0, uint32_t b1) {
    asm volatile(
        "mma.sync.aligned.m16n8k16.row.col.f32.f16.f16.f32 "
        "{%0,%1,%2,%3}, {%4,%5,%6,%7}, {%8,%9}, {%0,%1,%2,%3};"
        : "+f"(c[0]), "+f"(c[1]), "+f"(c[2]), "+f"(c[3])
        : "r"(a[0]), "r"(a[1]), "r"(a[2]), "r"(a[3]), "r"(b0), "r"(b1));
}

// ---------------------------------------------------------------------------
// Fused weight split: all 8 weights -> (hi, lo) fp16, one launch.
// Reads inputs in metadata order, writes to reordered dest offsets.
// ---------------------------------------------------------------------------
__global__ __launch_bounds__(256) void split_w_kernel(
    const float* __restrict__ w0, const float* __restrict__ w1,
    const float* __restrict__ w2, const float* __restrict__ w3,
    const float* __restrict__ w4, const float* __restrict__ w5,
    const float* __restrict__ w6, const float* __restrict__ w7,
    __half* __restrict__ hi, __half* __restrict__ lo)
{
    // input cumulative sizes in float4 units (metadata order)
    const int cum[8] = {65536, 1114112, 2162688, 2752512,
                        2818048, 3866624, 4915200, 5111808};
    // dest base offsets in float4 units (scratch order: w0,w4,w1,w2,w3,w5,w6,w7)
    const int dst[8] = {0, 131072, 1179648, 2228224,
                        65536, 2818048, 3866624, 4915200};
    int idx = blockIdx.x * 256 + threadIdx.x;
    if (idx >= 5111808) return;
    const float* srcs[8] = {w0, w1, w2, w3, w4, w5, w6, w7};
    int s = 0;
#pragma unroll
    for (int i = 0; i < 7; i++) s += (idx >= cum[i]);
    int local = idx - (s ? cum[s - 1] : 0);
    int d = dst[s] + local;
    float4 v = ((const float4*)srcs[s])[local];
    float f[4] = {v.x, v.y, v.z, v.w};
    __align__(8) __half h[4], l[4];
#pragma unroll
    for (int j = 0; j < 4; j++) {
        h[j] = __float2half(f[j]);
        l[j] = __float2half(f[j] - __half2float(h[j]));
    }
    ((uint2*)hi)[d] = *(const uint2*)h;
    ((uint2*)lo)[d] = *(const uint2*)l;
}

// x (LATENT, KCOLS) -> xt (KCOLS, LATENT), plain fp16
__global__ __launch_bounds__(256) void split_xT_kernel(
    const float* __restrict__ x, __half* __restrict__ out)
{
    int i = blockIdx.x * 256 + threadIdx.x;  // i = n*LATENT + f
    int f = i & (LATENT - 1);
    int n = i >> 7;
    out[i] = __float2half(x[(size_t)f * KCOLS + n]);
}

// ---------------------------------------------------------------------------
// HMMA split GEMM:  C = (Ah [+ Al]) @ B^T.
//   A = weights hi/lo fp16 (pitch Kd), B = fp16 activations (pitch bpitch).
//   Output TRANSPOSED [n][opitch]. mode 0: relu + fp16; 1: fp32 raw.
//   terms: 2 = hi+lo weight MMAs, 1 = hi only.
// CTA 128x128x32, 256 threads, warp tile 64x32, 3-stage cp.async, 2 CTAs/SM.
// ---------------------------------------------------------------------------
#define BM 128
#define BN 128
#define BK 32
#define GT 256
#define PITCH 80
#define TILE_B (128 * PITCH)      // 10240
#define OFF_AH 0
#define OFF_AL TILE_B
#define OFF_B  (2 * TILE_B)
#define STAGE_B (3 * TILE_B)      // 30720
#define NSTAGE 3
#define GEMM_SMEM (NSTAGE * STAGE_B)   // 92160

__device__ __forceinline__ void load_stage(
    const __half* __restrict__ Ah, const __half* __restrict__ Al,
    const __half* __restrict__ B, int Kd, int bpitch,
    int m0, int n0, int kk, uint32_t stage_sb, int tid)
{
#pragma unroll
    for (int i = 0; i < 6; i++) {
        const int c = tid + i * 256;
        const int row = c >> 2;
        const int cb = (c & 3) * 16;
        const __half* gp;
        uint32_t soff;
        if (row < 128) {
            gp = Ah + (size_t)(m0 + row) * Kd + kk;
            soff = OFF_AH + row * PITCH;
        } else if (row < 256) {
            gp = Al + (size_t)(m0 + row - 128) * Kd + kk;
            soff = OFF_AL + (row - 128) * PITCH;
        } else {
            gp = B + (size_t)(n0 + row - 256) * bpitch + kk;
            soff = OFF_B + (row - 256) * PITCH;
        }
        cp16(stage_sb + soff + cb, (const char*)gp + cb);
    }
}

__global__ __launch_bounds__(GT, 2) void gemm_hmma_kernel(
    const __half* __restrict__ A_hi, const __half* __restrict__ A_lo,
    const __half* __restrict__ B, __half* __restrict__ out_h,
    float* __restrict__ out_f32, int M, int Kd, int mode,
    int ktps, size_t out_stride, int bpitch, int opitch, int terms)
{
    extern __shared__ __align__(128) char smem[];
    const uint32_t sb = smem_u32(smem);
    const int tid = threadIdx.x;
    const int lane = tid & 31;
    const int wid = tid >> 5;                 // 0..7
    const int warp_m0 = (wid & 1) * 64;
    const int warp_n0 = (wid >> 1) * 32;
    const int m0 = blockIdx.y * BM;
    const int n0 = blockIdx.x * BN;
    const int KT = Kd / BK;
    const int ktb = blockIdx.z * ktps;
    const int L = min(KT - ktb, ktps);
    out_f32 += (size_t)blockIdx.z * out_stride;

    const int a_row = (lane & 7) + ((lane >> 3) & 1) * 8;
    const int a_kb  = (lane >> 4) * 16;
    const int b_row = (lane & 7) + (lane >> 4) * 8;
    const int b_kb  = ((lane >> 3) & 1) * 16;

    float acc[4][4][4];
#pragma unroll
    for (int mt = 0; mt < 4; mt++)
#pragma unroll
        for (int nt = 0; nt < 4; nt++)
#pragma unroll
            for (int i = 0; i < 4; i++) acc[mt][nt][i] = 0.0f;

    load_stage(A_hi, A_lo, B, Kd, bpitch, m0, n0, ktb * BK, sb, tid);
    CP_COMMIT();
    load_stage(A_hi, A_lo, B, Kd, bpitch, m0, n0, (ktb + 1) * BK, sb + STAGE_B, tid);
    CP_COMMIT();

    for (int kt = 0; kt < L; kt++) {
        asm volatile("cp.async.wait_group 1;" ::: "memory");
        __syncthreads();

        if (kt + 2 < L) {
            load_stage(A_hi, A_lo, B, Kd, bpitch, m0, n0, (ktb + kt + 2) * BK,
                       sb + ((kt + 2) % NSTAGE) * STAGE_B, tid);
        }
        CP_COMMIT();

        const uint32_t st = sb + (kt % NSTAGE) * STAGE_B;
#pragma unroll
        for (int ks = 0; ks < 2; ks++) {
            const int kb = ks * 32;
            uint32_t bq[2][4];
#pragma unroll
            for (int g = 0; g < 2; g++) {
                uint32_t rb = st + OFF_B + (warp_n0 + g * 16 + b_row) * PITCH + kb + b_kb;
                ldsm_x4(rb, bq[g]);
            }
#pragma unroll
            for (int mt = 0; mt < 4; mt++) {
                uint32_t ah[4], al[4];
                uint32_t ra = st + (warp_m0 + mt * 16 + a_row) * PITCH + kb + a_kb;
                ldsm_x4(ra + OFF_AH, ah);
                if (terms == 2) ldsm_x4(ra + OFF_AL, al);
#pragma unroll
                for (int nt = 0; nt < 4; nt++) {
                    const int g = nt >> 1, p = (nt & 1) * 2;
                    mma_f16(acc[mt][nt], ah, bq[g][p], bq[g][p + 1]);
                    if (terms == 2)
                        mma_f16(acc[mt][nt], al, bq[g][p], bq[g][p + 1]);
                }
            }
        }
    }

    // ---------------- epilogue: transpose via SMEM (128 x 132 fp32) --------
    __syncthreads();
    float* sC = (float*)smem;
    const int crow = lane >> 2, ccol = (lane & 3) * 2;
#pragma unroll
    for (int mt = 0; mt < 4; mt++)
#pragma unroll
        for (int nt = 0; nt < 4; nt++) {
            const int m_ = warp_m0 + mt * 16 + crow;
            const int n_ = warp_n0 + nt * 8 + ccol;
            const float* c = acc[mt][nt];
            sC[(size_t)n_ * 132 + m_]           = c[0];
            sC[(size_t)(n_ + 1) * 132 + m_]     = c[1];
            sC[(size_t)n_ * 132 + m_ + 8]       = c[2];
            sC[(size_t)(n_ + 1) * 132 + m_ + 8] = c[3];
        }
    __syncthreads();

    const int r  = tid >> 1;          // n row 0..127
    const int mh = (tid & 1) * 64;    // m half
    const size_t base = (size_t)(n0 + r) * opitch + m0 + mh;
    const float* srow = &sC[(size_t)r * 132 + mh];
    if (mode == 0) {
#pragma unroll
        for (int j0 = 0; j0 < 64; j0 += 8) {
            __align__(16) __half h8[8];
#pragma unroll
            for (int j = 0; j < 8; j++)
                h8[j] = __float2half(fmaxf(srow[j0 + j], 0.0f));
            *(uint4*)(out_h + base + j0) = *(const uint4*)h8;
        }
    } else {
#pragma unroll
        for (int j0 = 0; j0 < 64; j0 += 4) {
            float4 v;
            v.x = srow[j0 + 0]; v.y = srow[j0 + 1];
            v.z = srow[j0 + 2]; v.w = srow[j0 + 3];
            *(float4*)(out_f32 + base + j0) = v;
        }
    }
}

// ---------------------------------------------------------------------------
// expm (3x3) + output assembly; sums split-K partials (2 omega, 3 trans).
// ---------------------------------------------------------------------------
__device__ __forceinline__ void mm3(const float* X, const float* Y, float* Z) {
#pragma unroll
    for (int r = 0; r < 3; r++)
#pragma unroll
        for (int c = 0; c < 3; c++)
            Z[3 * r + c] = fmaf(X[3 * r + 0], Y[c],
                           fmaf(X[3 * r + 1], Y[3 + c], X[3 * r + 2] * Y[6 + c]));
}

__device__ void expm3(const float* A, float* E) {
    float n0 = fabsf(A[0]) + fabsf(A[1]) + fabsf(A[2]);
    float n1 = fabsf(A[3]) + fabsf(A[4]) + fabsf(A[5]);
    float n2 = fabsf(A[6]) + fabsf(A[7]) + fabsf(A[8]);
    float nrm = fmaxf(n0, fmaxf(n1, n2));
    int s = 0;
    if (nrm > 0.25f) {
        s = (int)ceilf(log2f(nrm * 4.0f));
        if (s < 0) s = 0;
    }
    float sc = exp2f((float)(-s));
    float B[9], T[9];
#pragma unroll
    for (int i = 0; i < 9; i++) B[i] = A[i] * sc;
#pragma unroll
    for (int i = 0; i < 9; i++) {
        T[i] = B[i];
        E[i] = ((i == 0) | (i == 4) | (i == 8)) ? 1.0f + B[i] : B[i];
    }
#pragma unroll
    for (int j = 2; j <= 10; j++) {
        float Tn[9];
        mm3(T, B, Tn);
        float inv = 1.0f / (float)j;
#pragma unroll
        for (int i = 0; i < 9; i++) { Tn[i] *= inv; E[i] += Tn[i]; T[i] = Tn[i]; }
    }
    for (int q = 0; q < s; q++) {
        float S[9];
        mm3(E, E, S);
#pragma unroll
        for (int i = 0; i < 9; i++) E[i] = S[i];
    }
}

__global__ __launch_bounds__(256) void expm_assemble_kernel(
    const float* __restrict__ omega_part, // 2 x (K, 9n)
    const float* __restrict__ trans_part, // 3 x (K, 3n)
    float* __restrict__ omega_out,        // (9n, K)
    float* __restrict__ transf,           // (12n, K)
    float* __restrict__ rot,              // (9n, K)
    float* __restrict__ trans_out)        // (3n, K)
{
    const int n = blockIdx.x * 256 + threadIdx.x;
    const int p = blockIdx.y;
    const size_t SO = (size_t)KCOLS * OMEGA_D;
    const size_t ST = (size_t)KCOLS * TRANZ_D;

    float Am[9];
    const size_t obase = (size_t)n * OMEGA_D + 9 * p;
#pragma unroll
    for (int j = 0; j < 9; j++)
        Am[j] = __ldg(omega_part + obase + j) + __ldg(omega_part + SO + obase + j);

    float E[9];
    expm3(Am, E);

#pragma unroll
    for (int j = 0; j < 9; j++) {
        omega_out[(size_t)(9 * p + j) * KCOLS + n] = Am[j];
        rot[(size_t)(9 * p + j) * KCOLS + n]       = E[j];
        transf[(size_t)(12 * p + j) * KCOLS + n]   = E[j];
    }
    const size_t tbase = (size_t)n * TRANZ_D + 3 * p;
#pragma unroll
    for (int c = 0; c < 3; c++) {
        float tv = __ldg(trans_part + tbase + c)
                 + __ldg(trans_part + ST + tbase + c)
                 + __ldg(trans_part + 2 * ST + tbase + c);
        trans_out[(size_t)(3 * p + c) * KCOLS + n]   = tv;
        transf[(size_t)(12 * p + 9 + c) * KCOLS + n] = tv;
    }
}

// ---------------------------------------------------------------------------
// kernel_launch
// ---------------------------------------------------------------------------
extern "C" void kernel_launch(void* const* d_in, const int* in_sizes, int n_in,
                              void* d_out, int out_size)
{
    const float* x = (const float*)d_in[0];
    const float* W[8];
    for (int i = 0; i < 8; i++) W[i] = (const float*)d_in[1 + i];

    // scratch weight element offsets (order: w0,w4,w1,w2,w3,w5,w6,w7)
    const size_t O_W04 = 0;                       // merged [4096, 128]
    const size_t O_W1  = 524288;
    const size_t O_W2  = O_W1 + 4194304;
    const size_t O_W3  = O_W2 + 4194304;
    const size_t O_W5  = O_W3 + 2359296;
    const size_t O_W6  = O_W5 + 4194304;
    const size_t O_W7  = O_W6 + 4194304;

    float* out    = (float*)d_out;
    float* omega  = out;
    float* transf = omega  + (size_t)OMEGA_D  * KCOLS;
    float* rot    = transf + (size_t)TRANSF_D * KCOLS;
    float* trans  = rot    + (size_t)OMEGA_D  * KCOLS;

    __half *w_hi, *w_lo, *xt, *act0, *a1, *a2;
    float *omega_part, *trans_part;
    cudaGetSymbolAddress((void**)&w_hi, g_w_hi);
    cudaGetSymbolAddress((void**)&w_lo, g_w_lo);
    cudaGetSymbolAddress((void**)&xt, g_xt);
    cudaGetSymbolAddress((void**)&act0, g_act0);
    cudaGetSymbolAddress((void**)&a1, g_act1);
    cudaGetSymbolAddress((void**)&a2, g_act2);
    cudaGetSymbolAddress((void**)&omega_part, g_omega_part);
    cudaGetSymbolAddress((void**)&trans_part, g_trans_part);

    cudaFuncSetAttribute(gemm_hmma_kernel,
                         cudaFuncAttributeMaxDynamicSharedMemorySize, GEMM_SMEM);

    // 1) fused weight split + xT convert
    split_w_kernel<<<(5111808 + 255) / 256, 256>>>(
        W[0], W[1], W[2], W[3], W[4], W[5], W[6], W[7], w_hi, w_lo);
    split_xT_kernel<<<(KCOLS * LATENT) / 256, 256>>>(x, xt);

    // 2) GEMM chain
    auto gemm = [&](size_t wo, const __half* b, __half* oh, float* of,
                    int M, int Kd, int mode, int zsplits, size_t ostride,
                    int bpitch, int opitch, int terms) {
        int KT = Kd / BK;
        int ktps = (KT + zsplits - 1) / zsplits;
        dim3 grid(KCOLS / BN, M / BM, zsplits);
        gemm_hmma_kernel<<<grid, GT, GEMM_SMEM>>>(
            w_hi + wo, w_lo + wo, b, oh, of,
            M, Kd, mode, ktps, ostride, bpitch, opitch, terms);
    };

    // merged first layer: [w0;w4] (M=4096) @ xt -> act0 [n][4096]
    gemm(O_W04, xt, act0, nullptr, 4096, LATENT, 0, 1, 0, LATENT, 4096, 2);

    // omega branch
    gemm(O_W1, act0,        a1, nullptr, HIDDEN, HIDDEN, 0, 1, 0, 4096,   HIDDEN, 2);
    gemm(O_W2, a1,          a2, nullptr, HIDDEN, HIDDEN, 0, 1, 0, HIDDEN, HIDDEN, 2);
    gemm(O_W3, a2, nullptr, omega_part, OMEGA_D, HIDDEN, 1, 2,
         (size_t)KCOLS * OMEGA_D, HIDDEN, OMEGA_D, 1);

    // translation branch (reads second half of act0)
    gemm(O_W5, act0 + HIDDEN, a1, nullptr, HIDDEN, HIDDEN, 0, 1, 0, 4096,   HIDDEN, 2);
    gemm(O_W6, a1,            a2, nullptr, HIDDEN, HIDDEN, 0, 1, 0, HIDDEN, HIDDEN, 2);
    gemm(O_W7, a2, nullptr, trans_part, TRANZ_D, HIDDEN, 1, 3,
         (size_t)KCOLS * TRANZ_D, HIDDEN, TRANZ_D, 1);

    // 3) expm + assembly
    dim3 ge(KCOLS / 256, NPARTS);
    expm_assemble_kernel<<<ge, 256>>>(omega_part, trans_part, omega, transf,
                                      rot, trans);
}

// round 10
// speedup vs baseline: 1.2398x; 1.0774x over previous
#include <cuda_runtime.h>
#include <cuda_fp16.h>
#include <cstdint>

#define LATENT   128
#define HIDDEN   2048
#define NPARTS   128
#define KCOLS    2048
#define OMEGA_D  1152
#define TRANZ_D  384
#define TRANSF_D 1536

// ---------------------------------------------------------------------------
// Scratch (__device__ globals; allocation-guard-safe)
// ---------------------------------------------------------------------------
#define W_TOTAL (2048*128 + 2048*2048 + 2048*2048 + 1152*2048 + \
                 2048*128 + 2048*2048 + 2048*2048 + 384*2048)

__device__ __half g_w_hi[W_TOTAL];
__device__ __half g_w_lo[W_TOTAL];
__device__ __half g_act[2][HIDDEN * KCOLS];     // plain fp16 activations
__device__ __half g_xt[KCOLS * LATENT];
__device__ float g_omega_part[2 * (size_t)KCOLS * OMEGA_D];
__device__ float g_trans_part[3 * (size_t)KCOLS * TRANZ_D];

// ---------------------------------------------------------------------------
// PTX helpers (base ISA: ldmatrix / mma.sync / cp.async)
// ---------------------------------------------------------------------------
__device__ __forceinline__ uint32_t smem_u32(const void* p) {
    uint32_t a;
    asm("{ .reg .u64 t; cvta.to.shared.u64 t, %1; cvt.u32.u64 %0, t; }" : "=r"(a) : "l"(p));
    return a;
}
__device__ __forceinline__ void cp16(uint32_t s, const void* g) {
    asm volatile("cp.async.cg.shared.global [%0], [%1], 16;" :: "r"(s), "l"(g) : "memory");
}
#define CP_COMMIT() asm volatile("cp.async.commit_group;" ::: "memory")

__device__ __forceinline__ void ldsm_x4(uint32_t addr, uint32_t* r) {
    asm volatile("ldmatrix.sync.aligned.m8n8.x4.shared.b16 {%0,%1,%2,%3}, [%4];"
                 : "=r"(r[0]), "=r"(r[1]), "=r"(r[2]), "=r"(r[3]) : "r"(addr));
}
__device__ __forceinline__ void mma_f16(float* c, const uint32_t* a,
                                        uint32_t b0, uint32_t b1) {
    asm volatile(
        "mma.sync.aligned.m16n8k16.row.col.f32.f16.f16.f32 "
        "{%0,%1,%2,%3}, {%4,%5,%6,%7}, {%8,%9}, {%0,%1,%2,%3};"
        : "+f"(c[0]), "+f"(c[1]), "+f"(c[2]), "+f"(c[3])
        : "r"(a[0]), "r"(a[1]), "r"(a[2]), "r"(a[3]), "r"(b0), "r"(b1));
}

// ---------------------------------------------------------------------------
// Fused weight split: all 8 weights -> (hi, lo) fp16, one launch.
// ---------------------------------------------------------------------------
__global__ __launch_bounds__(256) void split_w_kernel(
    const float* __restrict__ w0, const float* __restrict__ w1,
    const float* __restrict__ w2, const float* __restrict__ w3,
    const float* __restrict__ w4, const float* __restrict__ w5,
    const float* __restrict__ w6, const float* __restrict__ w7,
    __half* __restrict__ hi, __half* __restrict__ lo)
{
    const int cum[8] = {65536, 1114112, 2162688, 2752512,
                        2818048, 3866624, 4915200, 5111808};
    int idx = blockIdx.x * 256 + threadIdx.x;
    if (idx >= 5111808) return;
    const float* srcs[8] = {w0, w1, w2, w3, w4, w5, w6, w7};
    int s = 0;
#pragma unroll
    for (int i = 0; i < 7; i++) s += (idx >= cum[i]);
    int local = idx - (s ? cum[s - 1] : 0);
    float4 v = ((const float4*)srcs[s])[local];
    float f[4] = {v.x, v.y, v.z, v.w};
    __align__(8) __half h[4], l[4];
#pragma unroll
    for (int j = 0; j < 4; j++) {
        h[j] = __float2half(f[j]);
        l[j] = __float2half(f[j] - __half2float(h[j]));
    }
    ((uint2*)hi)[idx] = *(const uint2*)h;
    ((uint2*)lo)[idx] = *(const uint2*)l;
}

// x (LATENT, KCOLS) -> xt (KCOLS, LATENT), plain fp16
__global__ __launch_bounds__(256) void split_xT_kernel(
    const float* __restrict__ x, __half* __restrict__ out)
{
    int i = blockIdx.x * 256 + threadIdx.x;  // i = n*LATENT + f
    int f = i & (LATENT - 1);
    int n = i >> 7;
    out[i] = __float2half(x[(size_t)f * KCOLS + n]);
}

// ---------------------------------------------------------------------------
// HMMA split GEMM:  C = (Ah [+ Al]) @ B^T,  TERMS template-specialized.
// Output TRANSPOSED [n][M]. mode 0: relu + fp16; mode 1: fp32 raw.
// CTA 128x128x32, 256 threads, warp tile 64x32, 3-stage cp.async, 2 CTAs/SM.
// ---------------------------------------------------------------------------
#define BM 128
#define BN 128
#define BK 32
#define GT 256
#define PITCH 80
#define TILE_B (128 * PITCH)      // 10240
#define OFF_AH 0
#define OFF_AL TILE_B
#define OFF_B  (2 * TILE_B)
#define STAGE_B (3 * TILE_B)      // 30720
#define NSTAGE 3
#define GEMM_SMEM (NSTAGE * STAGE_B)   // 92160

__device__ __forceinline__ void load_stage(
    const __half* __restrict__ Ah, const __half* __restrict__ Al,
    const __half* __restrict__ B, int Kd, int m0, int n0, int kk,
    uint32_t stage_sb, int tid)
{
#pragma unroll
    for (int i = 0; i < 6; i++) {
        const int c = tid + i * 256;
        const int row = c >> 2;
        const int cb = (c & 3) * 16;
        const __half* gsrc;
        int grow;
        uint32_t soff;
        if (row < 128)      { gsrc = Ah; grow = m0 + row;       soff = OFF_AH + row * PITCH; }
        else if (row < 256) { gsrc = Al; grow = m0 + row - 128; soff = OFF_AL + (row - 128) * PITCH; }
        else                { gsrc = B;  grow = n0 + row - 256; soff = OFF_B  + (row - 256) * PITCH; }
        cp16(stage_sb + soff + cb,
             (const char*)(gsrc + (size_t)grow * Kd + kk) + cb);
    }
}

template <int TERMS>
__global__ __launch_bounds__(GT, 2) void gemm_hmma_kernel(
    const __half* __restrict__ A_hi, const __half* __restrict__ A_lo,
    const __half* __restrict__ B, __half* __restrict__ out_h,
    float* __restrict__ out_f32, int M, int Kd, int mode,
    int ktps, size_t out_stride)
{
    extern __shared__ __align__(128) char smem[];
    const uint32_t sb = smem_u32(smem);
    const int tid = threadIdx.x;
    const int lane = tid & 31;
    const int wid = tid >> 5;                 // 0..7
    const int warp_m0 = (wid & 1) * 64;
    const int warp_n0 = (wid >> 1) * 32;
    const int m0 = blockIdx.y * BM;
    const int n0 = blockIdx.x * BN;
    const int KT = Kd / BK;
    const int ktb = blockIdx.z * ktps;
    const int L = min(KT - ktb, ktps);
    out_f32 += (size_t)blockIdx.z * out_stride;

    const int a_row = (lane & 7) + ((lane >> 3) & 1) * 8;
    const int a_kb  = (lane >> 4) * 16;
    const int b_row = (lane & 7) + (lane >> 4) * 8;
    const int b_kb  = ((lane >> 3) & 1) * 16;

    float acc[4][4][4];
#pragma unroll
    for (int mt = 0; mt < 4; mt++)
#pragma unroll
        for (int nt = 0; nt < 4; nt++)
#pragma unroll
            for (int i = 0; i < 4; i++) acc[mt][nt][i] = 0.0f;

    load_stage(A_hi, A_lo, B, Kd, m0, n0, ktb * BK, sb, tid);
    CP_COMMIT();
    load_stage(A_hi, A_lo, B, Kd, m0, n0, (ktb + 1) * BK, sb + STAGE_B, tid);
    CP_COMMIT();

    for (int kt = 0; kt < L; kt++) {
        asm volatile("cp.async.wait_group 1;" ::: "memory");
        __syncthreads();

        if (kt + 2 < L) {
            load_stage(A_hi, A_lo, B, Kd, m0, n0, (ktb + kt + 2) * BK,
                       sb + ((kt + 2) % NSTAGE) * STAGE_B, tid);
        }
        CP_COMMIT();

        const uint32_t st = sb + (kt % NSTAGE) * STAGE_B;
#pragma unroll
        for (int ks = 0; ks < 2; ks++) {
            const int kb = ks * 32;
            uint32_t bq[2][4];
#pragma unroll
            for (int g = 0; g < 2; g++) {
                uint32_t rb = st + OFF_B + (warp_n0 + g * 16 + b_row) * PITCH + kb + b_kb;
                ldsm_x4(rb, bq[g]);
            }
#pragma unroll
            for (int mt = 0; mt < 4; mt++) {
                uint32_t ah[4], al[4];
                uint32_t ra = st + (warp_m0 + mt * 16 + a_row) * PITCH + kb + a_kb;
                ldsm_x4(ra + OFF_AH, ah);
                if (TERMS == 2) ldsm_x4(ra + OFF_AL, al);
#pragma unroll
                for (int nt = 0; nt < 4; nt++) {
                    const int g = nt >> 1, p = (nt & 1) * 2;
                    mma_f16(acc[mt][nt], ah, bq[g][p], bq[g][p + 1]);
                    if (TERMS == 2)
                        mma_f16(acc[mt][nt], al, bq[g][p], bq[g][p + 1]);
                }
            }
        }
    }

    // ---------------- epilogue: transpose via SMEM (128 x 132 fp32) --------
    __syncthreads();
    float* sC = (float*)smem;
    const int crow = lane >> 2, ccol = (lane & 3) * 2;
#pragma unroll
    for (int mt = 0; mt < 4; mt++)
#pragma unroll
        for (int nt = 0; nt < 4; nt++) {
            const int m_ = warp_m0 + mt * 16 + crow;
            const int n_ = warp_n0 + nt * 8 + ccol;
            const float* c = acc[mt][nt];
            sC[(size_t)n_ * 132 + m_]           = c[0];
            sC[(size_t)(n_ + 1) * 132 + m_]     = c[1];
            sC[(size_t)n_ * 132 + m_ + 8]       = c[2];
            sC[(size_t)(n_ + 1) * 132 + m_ + 8] = c[3];
        }
    __syncthreads();

    const int r  = tid >> 1;          // n row 0..127
    const int mh = (tid & 1) * 64;    // m half
    const size_t base = (size_t)(n0 + r) * M + m0 + mh;
    const float* srow = &sC[(size_t)r * 132 + mh];
    if (mode == 0) {
#pragma unroll
        for (int j0 = 0; j0 < 64; j0 += 8) {
            __align__(16) __half h8[8];
#pragma unroll
            for (int j = 0; j < 8; j++)
                h8[j] = __float2half(fmaxf(srow[j0 + j], 0.0f));
            *(uint4*)(out_h + base + j0) = *(const uint4*)h8;
        }
    } else {
#pragma unroll
        for (int j0 = 0; j0 < 64; j0 += 4) {
            float4 v;
            v.x = srow[j0 + 0]; v.y = srow[j0 + 1];
            v.z = srow[j0 + 2]; v.w = srow[j0 + 3];
            *(float4*)(out_f32 + base + j0) = v;
        }
    }
}

// ---------------------------------------------------------------------------
// expm (3x3) + output assembly; sums split-K partials (2 omega, 3 trans).
// ---------------------------------------------------------------------------
__device__ __forceinline__ void mm3(const float* X, const float* Y, float* Z) {
#pragma unroll
    for (int r = 0; r < 3; r++)
#pragma unroll
        for (int c = 0; c < 3; c++)
            Z[3 * r + c] = fmaf(X[3 * r + 0], Y[c],
                           fmaf(X[3 * r + 1], Y[3 + c], X[3 * r + 2] * Y[6 + c]));
}

__device__ void expm3(const float* A, float* E) {
    float n0 = fabsf(A[0]) + fabsf(A[1]) + fabsf(A[2]);
    float n1 = fabsf(A[3]) + fabsf(A[4]) + fabsf(A[5]);
    float n2 = fabsf(A[6]) + fabsf(A[7]) + fabsf(A[8]);
    float nrm = fmaxf(n0, fmaxf(n1, n2));
    int s = 0;
    if (nrm > 0.25f) {
        s = (int)ceilf(log2f(nrm * 4.0f));
        if (s < 0) s = 0;
    }
    float sc = exp2f((float)(-s));
    float B[9], T[9];
#pragma unroll
    for (int i = 0; i < 9; i++) B[i] = A[i] * sc;
#pragma unroll
    for (int i = 0; i < 9; i++) {
        T[i] = B[i];
        E[i] = ((i == 0) | (i == 4) | (i == 8)) ? 1.0f + B[i] : B[i];
    }
#pragma unroll
    for (int j = 2; j <= 10; j++) {
        float Tn[9];
        mm3(T, B, Tn);
        float inv = 1.0f / (float)j;
#pragma unroll
        for (int i = 0; i < 9; i++) { Tn[i] *= inv; E[i] += Tn[i]; T[i] = Tn[i]; }
    }
    for (int q = 0; q < s; q++) {
        float S[9];
        mm3(E, E, S);
#pragma unroll
        for (int i = 0; i < 9; i++) E[i] = S[i];
    }
}

__global__ __launch_bounds__(256) void expm_assemble_kernel(
    const float* __restrict__ omega_part, // 2 x (K, 9n)
    const float* __restrict__ trans_part, // 3 x (K, 3n)
    float* __restrict__ omega_out,        // (9n, K)
    float* __restrict__ transf,           // (12n, K)
    float* __restrict__ rot,              // (9n, K)
    float* __restrict__ trans_out)        // (3n, K)
{
    const int n = blockIdx.x * 256 + threadIdx.x;
    const int p = blockIdx.y;
    const size_t SO = (size_t)KCOLS * OMEGA_D;
    const size_t ST = (size_t)KCOLS * TRANZ_D;

    float Am[9];
    const size_t obase = (size_t)n * OMEGA_D + 9 * p;
#pragma unroll
    for (int j = 0; j < 9; j++)
        Am[j] = __ldg(omega_part + obase + j) + __ldg(omega_part + SO + obase + j);

    float E[9];
    expm3(Am, E);

#pragma unroll
    for (int j = 0; j < 9; j++) {
        omega_out[(size_t)(9 * p + j) * KCOLS + n] = Am[j];
        rot[(size_t)(9 * p + j) * KCOLS + n]       = E[j];
        transf[(size_t)(12 * p + j) * KCOLS + n]   = E[j];
    }
    const size_t tbase = (size_t)n * TRANZ_D + 3 * p;
#pragma unroll
    for (int c = 0; c < 3; c++) {
        float tv = __ldg(trans_part + tbase + c)
                 + __ldg(trans_part + ST + tbase + c)
                 + __ldg(trans_part + 2 * ST + tbase + c);
        trans_out[(size_t)(3 * p + c) * KCOLS + n]   = tv;
        transf[(size_t)(12 * p + 9 + c) * KCOLS + n] = tv;
    }
}

// ---------------------------------------------------------------------------
// kernel_launch
// ---------------------------------------------------------------------------
extern "C" void kernel_launch(void* const* d_in, const int* in_sizes, int n_in,
                              void* d_out, int out_size)
{
    const float* x = (const float*)d_in[0];
    const float* W[8];
    for (int i = 0; i < 8; i++) W[i] = (const float*)d_in[1 + i];

    const int wsz[8] = {2048 * 128, 2048 * 2048, 2048 * 2048, 1152 * 2048,
                        2048 * 128, 2048 * 2048, 2048 * 2048, 384 * 2048};
    size_t woff[8];
    size_t acc = 0;
    for (int i = 0; i < 8; i++) { woff[i] = acc; acc += wsz[i]; }

    float* out    = (float*)d_out;
    float* omega  = out;
    float* transf = omega  + (size_t)OMEGA_D  * KCOLS;
    float* rot    = transf + (size_t)TRANSF_D * KCOLS;
    float* trans  = rot    + (size_t)OMEGA_D  * KCOLS;

    __half *w_hi, *w_lo, *xt, *a0, *a1;
    float *omega_part, *trans_part;
    cudaGetSymbolAddress((void**)&w_hi, g_w_hi);
    cudaGetSymbolAddress((void**)&w_lo, g_w_lo);
    cudaGetSymbolAddress((void**)&xt, g_xt);
    {
        __half* p;
        cudaGetSymbolAddress((void**)&p, g_act);
        a0 = p; a1 = p + (size_t)HIDDEN * KCOLS;
    }
    cudaGetSymbolAddress((void**)&omega_part, g_omega_part);
    cudaGetSymbolAddress((void**)&trans_part, g_trans_part);

    cudaFuncSetAttribute(gemm_hmma_kernel<2>,
                         cudaFuncAttributeMaxDynamicSharedMemorySize, GEMM_SMEM);
    cudaFuncSetAttribute(gemm_hmma_kernel<1>,
                         cudaFuncAttributeMaxDynamicSharedMemorySize, GEMM_SMEM);

    // 1) fused weight split + xT convert
    split_w_kernel<<<(5111808 + 255) / 256, 256>>>(
        W[0], W[1], W[2], W[3], W[4], W[5], W[6], W[7], w_hi, w_lo);
    split_xT_kernel<<<(KCOLS * LATENT) / 256, 256>>>(x, xt);

    // 2) GEMM chains
    auto gemm2 = [&](int wi, const __half* b, __half* oh, float* of,
                     int M, int Kd, int mode, int zsplits, size_t ostride) {
        int KT = Kd / BK;
        int ktps = (KT + zsplits - 1) / zsplits;
        dim3 grid(KCOLS / BN, M / BM, zsplits);
        gemm_hmma_kernel<2><<<grid, GT, GEMM_SMEM>>>(
            w_hi + woff[wi], w_lo + woff[wi], b, oh, of,
            M, Kd, mode, ktps, ostride);
    };
    auto gemm1 = [&](int wi, const __half* b, __half* oh, float* of,
                     int M, int Kd, int mode, int zsplits, size_t ostride) {
        int KT = Kd / BK;
        int ktps = (KT + zsplits - 1) / zsplits;
        dim3 grid(KCOLS / BN, M / BM, zsplits);
        gemm_hmma_kernel<1><<<grid, GT, GEMM_SMEM>>>(
            w_hi + woff[wi], w_lo + woff[wi], b, oh, of,
            M, Kd, mode, ktps, ostride);
    };

    // omega branch (layer3 hi-only, split-K x2)
    gemm2(0, xt, a0, nullptr, HIDDEN,  LATENT, 0, 1, 0);
    gemm2(1, a0, a1, nullptr, HIDDEN,  HIDDEN, 0, 1, 0);
    gemm2(2, a1, a0, nullptr, HIDDEN,  HIDDEN, 0, 1, 0);
    gemm1(3, a0, nullptr, omega_part, OMEGA_D, HIDDEN, 1, 2,
          (size_t)KCOLS * OMEGA_D);
    // translation branch (layer7 hi-only, split-K x3)
    gemm2(4, xt, a0, nullptr, HIDDEN,  LATENT, 0, 1, 0);
    gemm2(5, a0, a1, nullptr, HIDDEN,  HIDDEN, 0, 1, 0);
    gemm2(6, a1, a0, nullptr, HIDDEN,  HIDDEN, 0, 1, 0);
    gemm1(7, a0, nullptr, trans_part, TRANZ_D, HIDDEN, 1, 3,
          (size_t)KCOLS * TRANZ_D);

    // 3) expm + assembly
    dim3 ge(KCOLS / 256, NPARTS);
    expm_assemble_kernel<<<ge, 256>>>(omega_part, trans_part, omega, transf,
                                      rot, trans);
}

// round 11
// speedup vs baseline: 1.4645x; 1.1812x over previous
#include <cuda_runtime.h>
#include <cuda_fp16.h>
#include <cstdint>

#define LATENT   128
#define HIDDEN   2048
#define NPARTS   128
#define KCOLS    2048
#define OMEGA_D  1152
#define TRANZ_D  384
#define TRANSF_D 1536

// ---------------------------------------------------------------------------
// Scratch (__device__ globals; allocation-guard-safe)
// ---------------------------------------------------------------------------
#define W_TOTAL (2048*128 + 2048*2048 + 2048*2048 + 1152*2048 + \
                 2048*128 + 2048*2048 + 2048*2048 + 384*2048)

__device__ __half g_w_hi[W_TOTAL];
__device__ __half g_w_lo[W_TOTAL];
__device__ __half g_act[2][HIDDEN * KCOLS];     // plain fp16 activations
__device__ __half g_xt[KCOLS * LATENT];
__device__ float g_omega_part[2 * (size_t)KCOLS * OMEGA_D];
__device__ float g_trans_part[3 * (size_t)KCOLS * TRANZ_D];

// ---------------------------------------------------------------------------
// PTX helpers (base ISA: ldmatrix / mma.sync / cp.async)
// ---------------------------------------------------------------------------
__device__ __forceinline__ uint32_t smem_u32(const void* p) {
    uint32_t a;
    asm("{ .reg .u64 t; cvta.to.shared.u64 t, %1; cvt.u32.u64 %0, t; }" : "=r"(a) : "l"(p));
    return a;
}
__device__ __forceinline__ void cp16(uint32_t s, const void* g) {
    asm volatile("cp.async.cg.shared.global [%0], [%1], 16;" :: "r"(s), "l"(g) : "memory");
}
#define CP_COMMIT() asm volatile("cp.async.commit_group;" ::: "memory")

__device__ __forceinline__ void ldsm_x4(uint32_t addr, uint32_t* r) {
    asm volatile("ldmatrix.sync.aligned.m8n8.x4.shared.b16 {%0,%1,%2,%3}, [%4];"
                 : "=r"(r[0]), "=r"(r[1]), "=r"(r[2]), "=r"(r[3]) : "r"(addr));
}
__device__ __forceinline__ void mma_f16(float* c, const uint32_t* a,
                                        uint32_t b0, uint32_t b1) {
    asm volatile(
        "mma.sync.aligned.m16n8k16.row.col.f32.f16.f16.f32 "
        "{%0,%1,%2,%3}, {%4,%5,%6,%7}, {%8,%9}, {%0,%1,%2,%3};"
        : "+f"(c[0]), "+f"(c[1]), "+f"(c[2]), "+f"(c[3])
        : "r"(a[0]), "r"(a[1]), "r"(a[2]), "r"(a[3]), "r"(b0), "r"(b1));
}

// ---------------------------------------------------------------------------
// Fused weight split: all 8 weights -> (hi, lo) fp16, one launch.
// ---------------------------------------------------------------------------
__global__ __launch_bounds__(256) void split_w_kernel(
    const float* __restrict__ w0, const float* __restrict__ w1,
    const float* __restrict__ w2, const float* __restrict__ w3,
    const float* __restrict__ w4, const float* __restrict__ w5,
    const float* __restrict__ w6, const float* __restrict__ w7,
    __half* __restrict__ hi, __half* __restrict__ lo)
{
    const int cum[8] = {65536, 1114112, 2162688, 2752512,
                        2818048, 3866624, 4915200, 5111808};
    int idx = blockIdx.x * 256 + threadIdx.x;
    if (idx >= 5111808) return;
    const float* srcs[8] = {w0, w1, w2, w3, w4, w5, w6, w7};
    int s = 0;
#pragma unroll
    for (int i = 0; i < 7; i++) s += (idx >= cum[i]);
    int local = idx - (s ? cum[s - 1] : 0);
    float4 v = ((const float4*)srcs[s])[local];
    float f[4] = {v.x, v.y, v.z, v.w};
    __align__(8) __half h[4], l[4];
#pragma unroll
    for (int j = 0; j < 4; j++) {
        h[j] = __float2half(f[j]);
        l[j] = __float2half(f[j] - __half2float(h[j]));
    }
    ((uint2*)hi)[idx] = *(const uint2*)h;
    ((uint2*)lo)[idx] = *(const uint2*)l;
}

// x (LATENT, KCOLS) -> xt (KCOLS, LATENT), plain fp16
__global__ __launch_bounds__(256) void split_xT_kernel(
    const float* __restrict__ x, __half* __restrict__ out)
{
    int i = blockIdx.x * 256 + threadIdx.x;  // i = n*LATENT + f
    int f = i & (LATENT - 1);
    int n = i >> 7;
    out[i] = __float2half(x[(size_t)f * KCOLS + n]);
}

// ---------------------------------------------------------------------------
// HMMA split GEMM:  C = (Ah [+ Al]) @ B^T,  TERMS template-specialized.
// Output TRANSPOSED [n][M]. mode 0: relu + fp16; mode 1: fp32 raw.
// CTA 128x128x32, 256 threads, warp tile 64x32, 3-stage cp.async, 2 CTAs/SM.
// ---------------------------------------------------------------------------
#define BM 128
#define BN 128
#define BK 32
#define GT 256
#define PITCH 80
#define TILE_B (128 * PITCH)      // 10240
#define OFF_AH 0
#define OFF_AL TILE_B
#define OFF_B  (2 * TILE_B)
#define STAGE_B (3 * TILE_B)      // 30720
#define NSTAGE 3
#define GEMM_SMEM (NSTAGE * STAGE_B)   // 92160

template <int TERMS>
__device__ __forceinline__ void load_stage(
    const __half* __restrict__ Ah, const __half* __restrict__ Al,
    const __half* __restrict__ B, int Kd, int m0, int n0, int kk,
    uint32_t stage_sb, int tid)
{
    if (TERMS == 2) {
        // 384 rows (Ah 128, Al 128, B 128), 4 x 16B chunks each.
#pragma unroll
        for (int i = 0; i < 6; i++) {
            const int c = tid + i * 256;
            const int row = c >> 2;
            const int cb = (c & 3) * 16;
            const __half* gsrc;
            int grow;
            uint32_t soff;
            if (row < 128)      { gsrc = Ah; grow = m0 + row;       soff = OFF_AH + row * PITCH; }
            else if (row < 256) { gsrc = Al; grow = m0 + row - 128; soff = OFF_AL + (row - 128) * PITCH; }
            else                { gsrc = B;  grow = n0 + row - 256; soff = OFF_B  + (row - 256) * PITCH; }
            cp16(stage_sb + soff + cb,
                 (const char*)(gsrc + (size_t)grow * Kd + kk) + cb);
        }
    } else {
        // 256 rows (Ah 128, B 128), Al slots untouched.
#pragma unroll
        for (int i = 0; i < 4; i++) {
            const int c = tid + i * 256;
            const int row = c >> 2;
            const int cb = (c & 3) * 16;
            const __half* gsrc;
            int grow;
            uint32_t soff;
            if (row < 128) { gsrc = Ah; grow = m0 + row;       soff = OFF_AH + row * PITCH; }
            else           { gsrc = B;  grow = n0 + row - 128; soff = OFF_B  + (row - 128) * PITCH; }
            cp16(stage_sb + soff + cb,
                 (const char*)(gsrc + (size_t)grow * Kd + kk) + cb);
        }
    }
}

template <int TERMS>
__global__ __launch_bounds__(GT, 2) void gemm_hmma_kernel(
    const __half* __restrict__ A_hi, const __half* __restrict__ A_lo,
    const __half* __restrict__ B, __half* __restrict__ out_h,
    float* __restrict__ out_f32, int M, int Kd, int mode,
    int ktps, size_t out_stride)
{
    extern __shared__ __align__(128) char smem[];
    const uint32_t sb = smem_u32(smem);
    const int tid = threadIdx.x;
    const int lane = tid & 31;
    const int wid = tid >> 5;                 // 0..7
    const int warp_m0 = (wid & 1) * 64;
    const int warp_n0 = (wid >> 1) * 32;
    const int m0 = blockIdx.y * BM;
    const int n0 = blockIdx.x * BN;
    const int KT = Kd / BK;
    const int ktb = blockIdx.z * ktps;
    const int L = min(KT - ktb, ktps);
    out_f32 += (size_t)blockIdx.z * out_stride;

    const int a_row = (lane & 7) + ((lane >> 3) & 1) * 8;
    const int a_kb  = (lane >> 4) * 16;
    const int b_row = (lane & 7) + (lane >> 4) * 8;
    const int b_kb  = ((lane >> 3) & 1) * 16;

    float acc[4][4][4];
#pragma unroll
    for (int mt = 0; mt < 4; mt++)
#pragma unroll
        for (int nt = 0; nt < 4; nt++)
#pragma unroll
            for (int i = 0; i < 4; i++) acc[mt][nt][i] = 0.0f;

    load_stage<TERMS>(A_hi, A_lo, B, Kd, m0, n0, ktb * BK, sb, tid);
    CP_COMMIT();
    load_stage<TERMS>(A_hi, A_lo, B, Kd, m0, n0, (ktb + 1) * BK, sb + STAGE_B, tid);
    CP_COMMIT();

    for (int kt = 0; kt < L; kt++) {
        asm volatile("cp.async.wait_group 1;" ::: "memory");
        __syncthreads();

        if (kt + 2 < L) {
            load_stage<TERMS>(A_hi, A_lo, B, Kd, m0, n0, (ktb + kt + 2) * BK,
                              sb + ((kt + 2) % NSTAGE) * STAGE_B, tid);
        }
        CP_COMMIT();

        const uint32_t st = sb + (kt % NSTAGE) * STAGE_B;
#pragma unroll
        for (int ks = 0; ks < 2; ks++) {
            const int kb = ks * 32;
            uint32_t bq[2][4];
#pragma unroll
            for (int g = 0; g < 2; g++) {
                uint32_t rb = st + OFF_B + (warp_n0 + g * 16 + b_row) * PITCH + kb + b_kb;
                ldsm_x4(rb, bq[g]);
            }
#pragma unroll
            for (int mt = 0; mt < 4; mt++) {
                uint32_t ah[4], al[4];
                uint32_t ra = st + (warp_m0 + mt * 16 + a_row) * PITCH + kb + a_kb;
                ldsm_x4(ra + OFF_AH, ah);
                if (TERMS == 2) ldsm_x4(ra + OFF_AL, al);
#pragma unroll
                for (int nt = 0; nt < 4; nt++) {
                    const int g = nt >> 1, p = (nt & 1) * 2;
                    mma_f16(acc[mt][nt], ah, bq[g][p], bq[g][p + 1]);
                    if (TERMS == 2)
                        mma_f16(acc[mt][nt], al, bq[g][p], bq[g][p + 1]);
                }
            }
        }
    }

    // ---------------- epilogue: transpose via SMEM (128 x 132 fp32) --------
    __syncthreads();
    float* sC = (float*)smem;
    const int crow = lane >> 2, ccol = (lane & 3) * 2;
#pragma unroll
    for (int mt = 0; mt < 4; mt++)
#pragma unroll
        for (int nt = 0; nt < 4; nt++) {
            const int m_ = warp_m0 + mt * 16 + crow;
            const int n_ = warp_n0 + nt * 8 + ccol;
            const float* c = acc[mt][nt];
            sC[(size_t)n_ * 132 + m_]           = c[0];
            sC[(size_t)(n_ + 1) * 132 + m_]     = c[1];
            sC[(size_t)n_ * 132 + m_ + 8]       = c[2];
            sC[(size_t)(n_ + 1) * 132 + m_ + 8] = c[3];
        }
    __syncthreads();

    const int r  = tid >> 1;          // n row 0..127
    const int mh = (tid & 1) * 64;    // m half
    const size_t base = (size_t)(n0 + r) * M + m0 + mh;
    const float* srow = &sC[(size_t)r * 132 + mh];
    if (mode == 0) {
#pragma unroll
        for (int j0 = 0; j0 < 64; j0 += 8) {
            __align__(16) __half h8[8];
#pragma unroll
            for (int j = 0; j < 8; j++)
                h8[j] = __float2half(fmaxf(srow[j0 + j], 0.0f));
            *(uint4*)(out_h + base + j0) = *(const uint4*)h8;
        }
    } else {
#pragma unroll
        for (int j0 = 0; j0 < 64; j0 += 4) {
            float4 v;
            v.x = srow[j0 + 0]; v.y = srow[j0 + 1];
            v.z = srow[j0 + 2]; v.w = srow[j0 + 3];
            *(float4*)(out_f32 + base + j0) = v;
        }
    }
}

// ---------------------------------------------------------------------------
// expm (3x3) + output assembly; sums split-K partials (2 omega, 3 trans).
// ---------------------------------------------------------------------------
__device__ __forceinline__ void mm3(const float* X, const float* Y, float* Z) {
#pragma unroll
    for (int r = 0; r < 3; r++)
#pragma unroll
        for (int c = 0; c < 3; c++)
            Z[3 * r + c] = fmaf(X[3 * r + 0], Y[c],
                           fmaf(X[3 * r + 1], Y[3 + c], X[3 * r + 2] * Y[6 + c]));
}

__device__ void expm3(const float* A, float* E) {
    float n0 = fabsf(A[0]) + fabsf(A[1]) + fabsf(A[2]);
    float n1 = fabsf(A[3]) + fabsf(A[4]) + fabsf(A[5]);
    float n2 = fabsf(A[6]) + fabsf(A[7]) + fabsf(A[8]);
    float nrm = fmaxf(n0, fmaxf(n1, n2));
    int s = 0;
    if (nrm > 0.25f) {
        s = (int)ceilf(log2f(nrm * 4.0f));
        if (s < 0) s = 0;
    }
    float sc = exp2f((float)(-s));
    float B[9], T[9];
#pragma unroll
    for (int i = 0; i < 9; i++) B[i] = A[i] * sc;
#pragma unroll
    for (int i = 0; i < 9; i++) {
        T[i] = B[i];
        E[i] = ((i == 0) | (i == 4) | (i == 8)) ? 1.0f + B[i] : B[i];
    }
#pragma unroll
    for (int j = 2; j <= 10; j++) {
        float Tn[9];
        mm3(T, B, Tn);
        float inv = 1.0f / (float)j;
#pragma unroll
        for (int i = 0; i < 9; i++) { Tn[i] *= inv; E[i] += Tn[i]; T[i] = Tn[i]; }
    }
    for (int q = 0; q < s; q++) {
        float S[9];
        mm3(E, E, S);
#pragma unroll
        for (int i = 0; i < 9; i++) E[i] = S[i];
    }
}

__global__ __launch_bounds__(256) void expm_assemble_kernel(
    const float* __restrict__ omega_part, // 2 x (K, 9n)
    const float* __restrict__ trans_part, // 3 x (K, 3n)
    float* __restrict__ omega_out,        // (9n, K)
    float* __restrict__ transf,           // (12n, K)
    float* __restrict__ rot,              // (9n, K)
    float* __restrict__ trans_out)        // (3n, K)
{
    const int n = blockIdx.x * 256 + threadIdx.x;
    const int p = blockIdx.y;
    const size_t SO = (size_t)KCOLS * OMEGA_D;
    const size_t ST = (size_t)KCOLS * TRANZ_D;

    float Am[9];
    const size_t obase = (size_t)n * OMEGA_D + 9 * p;
#pragma unroll
    for (int j = 0; j < 9; j++)
        Am[j] = __ldg(omega_part + obase + j) + __ldg(omega_part + SO + obase + j);

    float E[9];
    expm3(Am, E);

#pragma unroll
    for (int j = 0; j < 9; j++) {
        omega_out[(size_t)(9 * p + j) * KCOLS + n] = Am[j];
        rot[(size_t)(9 * p + j) * KCOLS + n]       = E[j];
        transf[(size_t)(12 * p + j) * KCOLS + n]   = E[j];
    }
    const size_t tbase = (size_t)n * TRANZ_D + 3 * p;
#pragma unroll
    for (int c = 0; c < 3; c++) {
        float tv = __ldg(trans_part + tbase + c)
                 + __ldg(trans_part + ST + tbase + c)
                 + __ldg(trans_part + 2 * ST + tbase + c);
        trans_out[(size_t)(3 * p + c) * KCOLS + n]   = tv;
        transf[(size_t)(12 * p + 9 + c) * KCOLS + n] = tv;
    }
}

// ---------------------------------------------------------------------------
// kernel_launch
// ---------------------------------------------------------------------------
extern "C" void kernel_launch(void* const* d_in, const int* in_sizes, int n_in,
                              void* d_out, int out_size)
{
    const float* x = (const float*)d_in[0];
    const float* W[8];
    for (int i = 0; i < 8; i++) W[i] = (const float*)d_in[1 + i];

    const int wsz[8] = {2048 * 128, 2048 * 2048, 2048 * 2048, 1152 * 2048,
                        2048 * 128, 2048 * 2048, 2048 * 2048, 384 * 2048};
    size_t woff[8];
    size_t acc = 0;
    for (int i = 0; i < 8; i++) { woff[i] = acc; acc += wsz[i]; }

    float* out    = (float*)d_out;
    float* omega  = out;
    float* transf = omega  + (size_t)OMEGA_D  * KCOLS;
    float* rot    = transf + (size_t)TRANSF_D * KCOLS;
    float* trans  = rot    + (size_t)OMEGA_D  * KCOLS;

    __half *w_hi, *w_lo, *xt, *a0, *a1;
    float *omega_part, *trans_part;
    cudaGetSymbolAddress((void**)&w_hi, g_w_hi);
    cudaGetSymbolAddress((void**)&w_lo, g_w_lo);
    cudaGetSymbolAddress((void**)&xt, g_xt);
    {
        __half* p;
        cudaGetSymbolAddress((void**)&p, g_act);
        a0 = p; a1 = p + (size_t)HIDDEN * KCOLS;
    }
    cudaGetSymbolAddress((void**)&omega_part, g_omega_part);
    cudaGetSymbolAddress((void**)&trans_part, g_trans_part);

    cudaFuncSetAttribute(gemm_hmma_kernel<2>,
                         cudaFuncAttributeMaxDynamicSharedMemorySize, GEMM_SMEM);
    cudaFuncSetAttribute(gemm_hmma_kernel<1>,
                         cudaFuncAttributeMaxDynamicSharedMemorySize, GEMM_SMEM);

    // 1) fused weight split + xT convert
    split_w_kernel<<<(5111808 + 255) / 256, 256>>>(
        W[0], W[1], W[2], W[3], W[4], W[5], W[6], W[7], w_hi, w_lo);
    split_xT_kernel<<<(KCOLS * LATENT) / 256, 256>>>(x, xt);

    // 2) GEMM chains
    auto gemm2 = [&](int wi, const __half* b, __half* oh, float* of,
                     int M, int Kd, int mode, int zsplits, size_t ostride) {
        int KT = Kd / BK;
        int ktps = (KT + zsplits - 1) / zsplits;
        dim3 grid(KCOLS / BN, M / BM, zsplits);
        gemm_hmma_kernel<2><<<grid, GT, GEMM_SMEM>>>(
            w_hi + woff[wi], w_lo + woff[wi], b, oh, of,
            M, Kd, mode, ktps, ostride);
    };
    auto gemm1 = [&](int wi, const __half* b, __half* oh, float* of,
                     int M, int Kd, int mode, int zsplits, size_t ostride) {
        int KT = Kd / BK;
        int ktps = (KT + zsplits - 1) / zsplits;
        dim3 grid(KCOLS / BN, M / BM, zsplits);
        gemm_hmma_kernel<1><<<grid, GT, GEMM_SMEM>>>(
            w_hi + woff[wi], w_lo + woff[wi], b, oh, of,
            M, Kd, mode, ktps, ostride);
    };

    // omega branch (layer2 + layer3 hi-only; layer3 split-K x2)
    gemm2(0, xt, a0, nullptr, HIDDEN,  LATENT, 0, 1, 0);
    gemm2(1, a0, a1, nullptr, HIDDEN,  HIDDEN, 0, 1, 0);
    gemm1(2, a1, a0, nullptr, HIDDEN,  HIDDEN, 0, 1, 0);
    gemm1(3, a0, nullptr, omega_part, OMEGA_D, HIDDEN, 1, 2,
          (size_t)KCOLS * OMEGA_D);
    // translation branch (layer6 + layer7 hi-only; layer7 split-K x3)
    gemm2(4, xt, a0, nullptr, HIDDEN,  LATENT, 0, 1, 0);
    gemm2(5, a0, a1, nullptr, HIDDEN,  HIDDEN, 0, 1, 0);
    gemm1(6, a1, a0, nullptr, HIDDEN,  HIDDEN, 0, 1, 0);
    gemm1(7, a0, nullptr, trans_part, TRANZ_D, HIDDEN, 1, 3,
          (size_t)KCOLS * TRANZ_D);

    // 3) expm + assembly
    dim3 ge(KCOLS / 256, NPARTS);
    expm_assemble_kernel<<<ge, 256>>>(omega_part, trans_part, omega, transf,
                                      rot, trans);
}

// round 12
// speedup vs baseline: 1.7984x; 1.2279x over previous
#include <cuda_runtime.h>
#include <cuda_fp16.h>
#include <cstdint>

#define LATENT   128
#define HIDDEN   2048
#define NPARTS   128
#define KCOLS    2048
#define OMEGA_D  1152
#define TRANZ_D  384
#define TRANSF_D 1536

// ---------------------------------------------------------------------------
// Scratch (__device__ globals; allocation-guard-safe)
// ---------------------------------------------------------------------------
#define W_TOTAL (2048*128 + 2048*2048 + 2048*2048 + 1152*2048 + \
                 2048*128 + 2048*2048 + 2048*2048 + 384*2048)

__device__ __half g_w_hi[W_TOTAL];
__device__ __half g_w_lo[W_TOTAL];
__device__ __half g_act[2][HIDDEN * KCOLS];     // plain fp16 activations
__device__ __half g_xt[KCOLS * LATENT];
__device__ float g_omega_part[2 * (size_t)KCOLS * OMEGA_D];
__device__ float g_trans_part[3 * (size_t)KCOLS * TRANZ_D];

// ---------------------------------------------------------------------------
// PTX helpers (base ISA: ldmatrix / mma.sync / cp.async)
// ---------------------------------------------------------------------------
__device__ __forceinline__ uint32_t smem_u32(const void* p) {
    uint32_t a;
    asm("{ .reg .u64 t; cvta.to.shared.u64 t, %1; cvt.u32.u64 %0, t; }" : "=r"(a) : "l"(p));
    return a;
}
__device__ __forceinline__ void cp16(uint32_t s, const void* g) {
    asm volatile("cp.async.cg.shared.global [%0], [%1], 16;" :: "r"(s), "l"(g) : "memory");
}
#define CP_COMMIT() asm volatile("cp.async.commit_group;" ::: "memory")

__device__ __forceinline__ void ldsm_x4(uint32_t addr, uint32_t* r) {
    asm volatile("ldmatrix.sync.aligned.m8n8.x4.shared.b16 {%0,%1,%2,%3}, [%4];"
                 : "=r"(r[0]), "=r"(r[1]), "=r"(r[2]), "=r"(r[3]) : "r"(addr));
}
__device__ __forceinline__ void mma_f16(float* c, const uint32_t* a,
                                        uint32_t b0, uint32_t b1) {
    asm volatile(
        "mma.sync.aligned.m16n8k16.row.col.f32.f16.f16.f32 "
        "{%0,%1,%2,%3}, {%4,%5,%6,%7}, {%8,%9}, {%0,%1,%2,%3};"
        : "+f"(c[0]), "+f"(c[1]), "+f"(c[2]), "+f"(c[3])
        : "r"(a[0]), "r"(a[1]), "r"(a[2]), "r"(a[3]), "r"(b0), "r"(b1));
}

// ---------------------------------------------------------------------------
// Fused weight split: all 8 weights -> hi fp16 (lo only where consumed:
// segments 0 (w0) and 4 (w4); all other layers run hi-only GEMMs).
// ---------------------------------------------------------------------------
__global__ __launch_bounds__(256) void split_w_kernel(
    const float* __restrict__ w0, const float* __restrict__ w1,
    const float* __restrict__ w2, const float* __restrict__ w3,
    const float* __restrict__ w4, const float* __restrict__ w5,
    const float* __restrict__ w6, const float* __restrict__ w7,
    __half* __restrict__ hi, __half* __restrict__ lo)
{
    const int cum[8] = {65536, 1114112, 2162688, 2752512,
                        2818048, 3866624, 4915200, 5111808};
    int idx = blockIdx.x * 256 + threadIdx.x;
    if (idx >= 5111808) return;
    const float* srcs[8] = {w0, w1, w2, w3, w4, w5, w6, w7};
    int s = 0;
#pragma unroll
    for (int i = 0; i < 7; i++) s += (idx >= cum[i]);
    int local = idx - (s ? cum[s - 1] : 0);
    float4 v = ((const float4*)srcs[s])[local];
    float f[4] = {v.x, v.y, v.z, v.w};
    __align__(8) __half h[4], l[4];
#pragma unroll
    for (int j = 0; j < 4; j++) {
        h[j] = __float2half(f[j]);
        l[j] = __float2half(f[j] - __half2float(h[j]));
    }
    ((uint2*)hi)[idx] = *(const uint2*)h;
    if (s == 0 || s == 4)
        ((uint2*)lo)[idx] = *(const uint2*)l;
}

// x (LATENT, KCOLS) -> xt (KCOLS, LATENT), plain fp16
__global__ __launch_bounds__(256) void split_xT_kernel(
    const float* __restrict__ x, __half* __restrict__ out)
{
    int i = blockIdx.x * 256 + threadIdx.x;  // i = n*LATENT + f
    int f = i & (LATENT - 1);
    int n = i >> 7;
    out[i] = __float2half(x[(size_t)f * KCOLS + n]);
}

// ---------------------------------------------------------------------------
// HMMA split GEMM:  C = (Ah [+ Al]) @ B^T,  TERMS template-specialized.
// Output TRANSPOSED [n][M]. mode 0: relu + fp16; mode 1: fp32 raw.
// CTA 128x128x32, 256 threads, warp tile 64x32, 3-stage cp.async, 2 CTAs/SM.
// ---------------------------------------------------------------------------
#define BM 128
#define BN 128
#define BK 32
#define GT 256
#define PITCH 80
#define TILE_B (128 * PITCH)      // 10240
#define OFF_AH 0
#define OFF_AL TILE_B
#define OFF_B  (2 * TILE_B)
#define STAGE_B (3 * TILE_B)      // 30720
#define NSTAGE 3
#define GEMM_SMEM (NSTAGE * STAGE_B)   // 92160

template <int TERMS>
__device__ __forceinline__ void load_stage(
    const __half* __restrict__ Ah, const __half* __restrict__ Al,
    const __half* __restrict__ B, int Kd, int m0, int n0, int kk,
    uint32_t stage_sb, int tid)
{
    if (TERMS == 2) {
#pragma unroll
        for (int i = 0; i < 6; i++) {
            const int c = tid + i * 256;
            const int row = c >> 2;
            const int cb = (c & 3) * 16;
            const __half* gsrc;
            int grow;
            uint32_t soff;
            if (row < 128)      { gsrc = Ah; grow = m0 + row;       soff = OFF_AH + row * PITCH; }
            else if (row < 256) { gsrc = Al; grow = m0 + row - 128; soff = OFF_AL + (row - 128) * PITCH; }
            else                { gsrc = B;  grow = n0 + row - 256; soff = OFF_B  + (row - 256) * PITCH; }
            cp16(stage_sb + soff + cb,
                 (const char*)(gsrc + (size_t)grow * Kd + kk) + cb);
        }
    } else {
#pragma unroll
        for (int i = 0; i < 4; i++) {
            const int c = tid + i * 256;
            const int row = c >> 2;
            const int cb = (c & 3) * 16;
            const __half* gsrc;
            int grow;
            uint32_t soff;
            if (row < 128) { gsrc = Ah; grow = m0 + row;       soff = OFF_AH + row * PITCH; }
            else           { gsrc = B;  grow = n0 + row - 128; soff = OFF_B  + (row - 128) * PITCH; }
            cp16(stage_sb + soff + cb,
                 (const char*)(gsrc + (size_t)grow * Kd + kk) + cb);
        }
    }
}

template <int TERMS>
__global__ __launch_bounds__(GT, 2) void gemm_hmma_kernel(
    const __half* __restrict__ A_hi, const __half* __restrict__ A_lo,
    const __half* __restrict__ B, __half* __restrict__ out_h,
    float* __restrict__ out_f32, int M, int Kd, int mode,
    int ktps, size_t out_stride)
{
    extern __shared__ __align__(128) char smem[];
    const uint32_t sb = smem_u32(smem);
    const int tid = threadIdx.x;
    const int lane = tid & 31;
    const int wid = tid >> 5;                 // 0..7
    const int warp_m0 = (wid & 1) * 64;
    const int warp_n0 = (wid >> 1) * 32;
    const int m0 = blockIdx.y * BM;
    const int n0 = blockIdx.x * BN;
    const int KT = Kd / BK;
    const int ktb = blockIdx.z * ktps;
    const int L = min(KT - ktb, ktps);
    out_f32 += (size_t)blockIdx.z * out_stride;

    const int a_row = (lane & 7) + ((lane >> 3) & 1) * 8;
    const int a_kb  = (lane >> 4) * 16;
    const int b_row = (lane & 7) + (lane >> 4) * 8;
    const int b_kb  = ((lane >> 3) & 1) * 16;

    float acc[4][4][4];
#pragma unroll
    for (int mt = 0; mt < 4; mt++)
#pragma unroll
        for (int nt = 0; nt < 4; nt++)
#pragma unroll
            for (int i = 0; i < 4; i++) acc[mt][nt][i] = 0.0f;

    load_stage<TERMS>(A_hi, A_lo, B, Kd, m0, n0, ktb * BK, sb, tid);
    CP_COMMIT();
    load_stage<TERMS>(A_hi, A_lo, B, Kd, m0, n0, (ktb + 1) * BK, sb + STAGE_B, tid);
    CP_COMMIT();

    for (int kt = 0; kt < L; kt++) {
        asm volatile("cp.async.wait_group 1;" ::: "memory");
        __syncthreads();

        if (kt + 2 < L) {
            load_stage<TERMS>(A_hi, A_lo, B, Kd, m0, n0, (ktb + kt + 2) * BK,
                              sb + ((kt + 2) % NSTAGE) * STAGE_B, tid);
        }
        CP_COMMIT();

        const uint32_t st = sb + (kt % NSTAGE) * STAGE_B;
#pragma unroll
        for (int ks = 0; ks < 2; ks++) {
            const int kb = ks * 32;
            uint32_t bq[2][4];
#pragma unroll
            for (int g = 0; g < 2; g++) {
                uint32_t rb = st + OFF_B + (warp_n0 + g * 16 + b_row) * PITCH + kb + b_kb;
                ldsm_x4(rb, bq[g]);
            }
#pragma unroll
            for (int mt = 0; mt < 4; mt++) {
                uint32_t ah[4], al[4];
                uint32_t ra = st + (warp_m0 + mt * 16 + a_row) * PITCH + kb + a_kb;
                ldsm_x4(ra + OFF_AH, ah);
                if (TERMS == 2) ldsm_x4(ra + OFF_AL, al);
#pragma unroll
                for (int nt = 0; nt < 4; nt++) {
                    const int g = nt >> 1, p = (nt & 1) * 2;
                    mma_f16(acc[mt][nt], ah, bq[g][p], bq[g][p + 1]);
                    if (TERMS == 2)
                        mma_f16(acc[mt][nt], al, bq[g][p], bq[g][p + 1]);
                }
            }
        }
    }

    // ---------------- epilogue: transpose via SMEM (128 x 132 fp32) --------
    __syncthreads();
    float* sC = (float*)smem;
    const int crow = lane >> 2, ccol = (lane & 3) * 2;
#pragma unroll
    for (int mt = 0; mt < 4; mt++)
#pragma unroll
        for (int nt = 0; nt < 4; nt++) {
            const int m_ = warp_m0 + mt * 16 + crow;
            const int n_ = warp_n0 + nt * 8 + ccol;
            const float* c = acc[mt][nt];
            sC[(size_t)n_ * 132 + m_]           = c[0];
            sC[(size_t)(n_ + 1) * 132 + m_]     = c[1];
            sC[(size_t)n_ * 132 + m_ + 8]       = c[2];
            sC[(size_t)(n_ + 1) * 132 + m_ + 8] = c[3];
        }
    __syncthreads();

    const int r  = tid >> 1;          // n row 0..127
    const int mh = (tid & 1) * 64;    // m half
    const size_t base = (size_t)(n0 + r) * M + m0 + mh;
    const float* srow = &sC[(size_t)r * 132 + mh];
    if (mode == 0) {
#pragma unroll
        for (int j0 = 0; j0 < 64; j0 += 8) {
            __align__(16) __half h8[8];
#pragma unroll
            for (int j = 0; j < 8; j++)
                h8[j] = __float2half(fmaxf(srow[j0 + j], 0.0f));
            *(uint4*)(out_h + base + j0) = *(const uint4*)h8;
        }
    } else {
#pragma unroll
        for (int j0 = 0; j0 < 64; j0 += 4) {
            float4 v;
            v.x = srow[j0 + 0]; v.y = srow[j0 + 1];
            v.z = srow[j0 + 2]; v.w = srow[j0 + 3];
            *(float4*)(out_f32 + base + j0) = v;
        }
    }
}

// ---------------------------------------------------------------------------
// expm (3x3) + output assembly; sums split-K partials (2 omega, 3 trans).
// ---------------------------------------------------------------------------
__device__ __forceinline__ void mm3(const float* X, const float* Y, float* Z) {
#pragma unroll
    for (int r = 0; r < 3; r++)
#pragma unroll
        for (int c = 0; c < 3; c++)
            Z[3 * r + c] = fmaf(X[3 * r + 0], Y[c],
                           fmaf(X[3 * r + 1], Y[3 + c], X[3 * r + 2] * Y[6 + c]));
}

__device__ void expm3(const float* A, float* E) {
    float n0 = fabsf(A[0]) + fabsf(A[1]) + fabsf(A[2]);
    float n1 = fabsf(A[3]) + fabsf(A[4]) + fabsf(A[5]);
    float n2 = fabsf(A[6]) + fabsf(A[7]) + fabsf(A[8]);
    float nrm = fmaxf(n0, fmaxf(n1, n2));
    int s = 0;
    if (nrm > 0.25f) {
        s = (int)ceilf(log2f(nrm * 4.0f));
        if (s < 0) s = 0;
    }
    float sc = exp2f((float)(-s));
    float B[9], T[9];
#pragma unroll
    for (int i = 0; i < 9; i++) B[i] = A[i] * sc;
#pragma unroll
    for (int i = 0; i < 9; i++) {
        T[i] = B[i];
        E[i] = ((i == 0) | (i == 4) | (i == 8)) ? 1.0f + B[i] : B[i];
    }
#pragma unroll
    for (int j = 2; j <= 10; j++) {
        float Tn[9];
        mm3(T, B, Tn);
        float inv = 1.0f / (float)j;
#pragma unroll
        for (int i = 0; i < 9; i++) { Tn[i] *= inv; E[i] += Tn[i]; T[i] = Tn[i]; }
    }
    for (int q = 0; q < s; q++) {
        float S[9];
        mm3(E, E, S);
#pragma unroll
        for (int i = 0; i < 9; i++) E[i] = S[i];
    }
}

__global__ __launch_bounds__(256) void expm_assemble_kernel(
    const float* __restrict__ omega_part, // 2 x (K, 9n)
    const float* __restrict__ trans_part, // 3 x (K, 3n)
    float* __restrict__ omega_out,        // (9n, K)
    float* __restrict__ transf,           // (12n, K)
    float* __restrict__ rot,              // (9n, K)
    float* __restrict__ trans_out)        // (3n, K)
{
    const int n = blockIdx.x * 256 + threadIdx.x;
    const int p = blockIdx.y;
    const size_t SO = (size_t)KCOLS * OMEGA_D;
    const size_t ST = (size_t)KCOLS * TRANZ_D;

    float Am[9];
    const size_t obase = (size_t)n * OMEGA_D + 9 * p;
#pragma unroll
    for (int j = 0; j < 9; j++)
        Am[j] = __ldg(omega_part + obase + j) + __ldg(omega_part + SO + obase + j);

    float E[9];
    expm3(Am, E);

#pragma unroll
    for (int j = 0; j < 9; j++) {
        omega_out[(size_t)(9 * p + j) * KCOLS + n] = Am[j];
        rot[(size_t)(9 * p + j) * KCOLS + n]       = E[j];
        transf[(size_t)(12 * p + j) * KCOLS + n]   = E[j];
    }
    const size_t tbase = (size_t)n * TRANZ_D + 3 * p;
#pragma unroll
    for (int c = 0; c < 3; c++) {
        float tv = __ldg(trans_part + tbase + c)
                 + __ldg(trans_part + ST + tbase + c)
                 + __ldg(trans_part + 2 * ST + tbase + c);
        trans_out[(size_t)(3 * p + c) * KCOLS + n]   = tv;
        transf[(size_t)(12 * p + 9 + c) * KCOLS + n] = tv;
    }
}

// ---------------------------------------------------------------------------
// kernel_launch
// ---------------------------------------------------------------------------
extern "C" void kernel_launch(void* const* d_in, const int* in_sizes, int n_in,
                              void* d_out, int out_size)
{
    const float* x = (const float*)d_in[0];
    const float* W[8];
    for (int i = 0; i < 8; i++) W[i] = (const float*)d_in[1 + i];

    const int wsz[8] = {2048 * 128, 2048 * 2048, 2048 * 2048, 1152 * 2048,
                        2048 * 128, 2048 * 2048, 2048 * 2048, 384 * 2048};
    size_t woff[8];
    size_t acc = 0;
    for (int i = 0; i < 8; i++) { woff[i] = acc; acc += wsz[i]; }

    float* out    = (float*)d_out;
    float* omega  = out;
    float* transf = omega  + (size_t)OMEGA_D  * KCOLS;
    float* rot    = transf + (size_t)TRANSF_D * KCOLS;
    float* trans  = rot    + (size_t)OMEGA_D  * KCOLS;

    __half *w_hi, *w_lo, *xt, *a0, *a1;
    float *omega_part, *trans_part;
    cudaGetSymbolAddress((void**)&w_hi, g_w_hi);
    cudaGetSymbolAddress((void**)&w_lo, g_w_lo);
    cudaGetSymbolAddress((void**)&xt, g_xt);
    {
        __half* p;
        cudaGetSymbolAddress((void**)&p, g_act);
        a0 = p; a1 = p + (size_t)HIDDEN * KCOLS;
    }
    cudaGetSymbolAddress((void**)&omega_part, g_omega_part);
    cudaGetSymbolAddress((void**)&trans_part, g_trans_part);

    cudaFuncSetAttribute(gemm_hmma_kernel<2>,
                         cudaFuncAttributeMaxDynamicSharedMemorySize, GEMM_SMEM);
    cudaFuncSetAttribute(gemm_hmma_kernel<1>,
                         cudaFuncAttributeMaxDynamicSharedMemorySize, GEMM_SMEM);

    // 1) fused weight split + xT convert
    split_w_kernel<<<(5111808 + 255) / 256, 256>>>(
        W[0], W[1], W[2], W[3], W[4], W[5], W[6], W[7], w_hi, w_lo);
    split_xT_kernel<<<(KCOLS * LATENT) / 256, 256>>>(x, xt);

    // 2) GEMM chains
    auto gemm2 = [&](int wi, const __half* b, __half* oh, float* of,
                     int M, int Kd, int mode, int zsplits, size_t ostride) {
        int KT = Kd / BK;
        int ktps = (KT + zsplits - 1) / zsplits;
        dim3 grid(KCOLS / BN, M / BM, zsplits);
        gemm_hmma_kernel<2><<<grid, GT, GEMM_SMEM>>>(
            w_hi + woff[wi], w_lo + woff[wi], b, oh, of,
            M, Kd, mode, ktps, ostride);
    };
    auto gemm1 = [&](int wi, const __half* b, __half* oh, float* of,
                     int M, int Kd, int mode, int zsplits, size_t ostride) {
        int KT = Kd / BK;
        int ktps = (KT + zsplits - 1) / zsplits;
        dim3 grid(KCOLS / BN, M / BM, zsplits);
        gemm_hmma_kernel<1><<<grid, GT, GEMM_SMEM>>>(
            w_hi + woff[wi], w_lo + woff[wi], b, oh, of,
            M, Kd, mode, ktps, ostride);
    };

    // omega branch: layer0 2-term; layers 1,2,3 hi-only (layer3 split-K x2)
    gemm2(0, xt, a0, nullptr, HIDDEN,  LATENT, 0, 1, 0);
    gemm1(1, a0, a1, nullptr, HIDDEN,  HIDDEN, 0, 1, 0);
    gemm1(2, a1, a0, nullptr, HIDDEN,  HIDDEN, 0, 1, 0);
    gemm1(3, a0, nullptr, omega_part, OMEGA_D, HIDDEN, 1, 2,
          (size_t)KCOLS * OMEGA_D);
    // translation branch: layer4 2-term; layers 5,6,7 hi-only (layer7 split-K x3)
    gemm2(4, xt, a0, nullptr, HIDDEN,  LATENT, 0, 1, 0);
    gemm1(5, a0, a1, nullptr, HIDDEN,  HIDDEN, 0, 1, 0);
    gemm1(6, a1, a0, nullptr, HIDDEN,  HIDDEN, 0, 1, 0);
    gemm1(7, a0, nullptr, trans_part, TRANZ_D, HIDDEN, 1, 3,
          (size_t)KCOLS * TRANZ_D);

    // 3) expm + assembly
    dim3 ge(KCOLS / 256, NPARTS);
    expm_assemble_kernel<<<ge, 256>>>(omega_part, trans_part, omega, transf,
                                      rot, trans);
}

// round 13
// speedup vs baseline: 2.1239x; 1.1810x over previous
#include <cuda_runtime.h>
#include <cuda_fp16.h>
#include <cstdint>

#define LATENT   128
#define HIDDEN   2048
#define NPARTS   128
#define KCOLS    2048
#define OMEGA_D  1152
#define TRANZ_D  384
#define TRANSF_D 1536

// ---------------------------------------------------------------------------
// Scratch (__device__ globals; allocation-guard-safe)
// ---------------------------------------------------------------------------
#define W_TOTAL (2048*128 + 2048*2048 + 2048*2048 + 1152*2048 + \
                 2048*128 + 2048*2048 + 2048*2048 + 384*2048)

__device__ __half g_w_hi[W_TOTAL];
__device__ __half g_act[2][HIDDEN * KCOLS];     // plain fp16 activations
__device__ __half g_xt[KCOLS * LATENT];
__device__ float g_omega_part[2 * (size_t)KCOLS * OMEGA_D];  // [M][K] layout
__device__ float g_trans_part[3 * (size_t)KCOLS * TRANZ_D];  // [M][K] layout

// ---------------------------------------------------------------------------
// PTX helpers (base ISA: ldmatrix / mma.sync / cp.async)
// ---------------------------------------------------------------------------
__device__ __forceinline__ uint32_t smem_u32(const void* p) {
    uint32_t a;
    asm("{ .reg .u64 t; cvta.to.shared.u64 t, %1; cvt.u32.u64 %0, t; }" : "=r"(a) : "l"(p));
    return a;
}
__device__ __forceinline__ void cp16(uint32_t s, const void* g) {
    asm volatile("cp.async.cg.shared.global [%0], [%1], 16;" :: "r"(s), "l"(g) : "memory");
}
#define CP_COMMIT() asm volatile("cp.async.commit_group;" ::: "memory")

__device__ __forceinline__ void ldsm_x4(uint32_t addr, uint32_t* r) {
    asm volatile("ldmatrix.sync.aligned.m8n8.x4.shared.b16 {%0,%1,%2,%3}, [%4];"
                 : "=r"(r[0]), "=r"(r[1]), "=r"(r[2]), "=r"(r[3]) : "r"(addr));
}
__device__ __forceinline__ void mma_f16(float* c, const uint32_t* a,
                                        uint32_t b0, uint32_t b1) {
    asm volatile(
        "mma.sync.aligned.m16n8k16.row.col.f32.f16.f16.f32 "
        "{%0,%1,%2,%3}, {%4,%5,%6,%7}, {%8,%9}, {%0,%1,%2,%3};"
        : "+f"(c[0]), "+f"(c[1]), "+f"(c[2]), "+f"(c[3])
        : "r"(a[0]), "r"(a[1]), "r"(a[2]), "r"(a[3]), "r"(b0), "r"(b1));
}

// ---------------------------------------------------------------------------
// Weight convert: all 8 weights -> hi fp16, one launch, 4-way MLP.
// ---------------------------------------------------------------------------
#define W_CHUNKS 5111808            // total float4 chunks
#define W_STRIDE 1277952            // ceil(W_CHUNKS / 4)

__global__ __launch_bounds__(256) void convert_w_kernel(
    const float* __restrict__ w0, const float* __restrict__ w1,
    const float* __restrict__ w2, const float* __restrict__ w3,
    const float* __restrict__ w4, const float* __restrict__ w5,
    const float* __restrict__ w6, const float* __restrict__ w7,
    __half* __restrict__ hi)
{
    const int cum[8] = {65536, 1114112, 2162688, 2752512,
                        2818048, 3866624, 4915200, 5111808};
    const float* srcs[8] = {w0, w1, w2, w3, w4, w5, w6, w7};
    const int base = blockIdx.x * 256 + threadIdx.x;

    int   idxs[4];
    const float4* gp[4];
    bool  ok[4];
#pragma unroll
    for (int r = 0; r < 4; r++) {
        int idx = base + r * W_STRIDE;
        idxs[r] = idx;
        ok[r] = (idx < W_CHUNKS);
        if (ok[r]) {
            int s = 0;
#pragma unroll
            for (int i = 0; i < 7; i++) s += (idx >= cum[i]);
            int local = idx - (s ? cum[s - 1] : 0);
            gp[r] = (const float4*)srcs[s] + local;
        } else {
            gp[r] = (const float4*)w0;  // dummy
        }
    }
    float4 v[4];
#pragma unroll
    for (int r = 0; r < 4; r++)
        if (ok[r]) v[r] = *gp[r];
#pragma unroll
    for (int r = 0; r < 4; r++) {
        if (!ok[r]) continue;
        float f[4] = {v[r].x, v[r].y, v[r].z, v[r].w};
        __align__(8) __half h[4];
#pragma unroll
        for (int j = 0; j < 4; j++) h[j] = __float2half(f[j]);
        ((uint2*)hi)[idxs[r]] = *(const uint2*)h;
    }
}

// x (LATENT, KCOLS) -> xt (KCOLS, LATENT), plain fp16
__global__ __launch_bounds__(256) void split_xT_kernel(
    const float* __restrict__ x, __half* __restrict__ out)
{
    int i = blockIdx.x * 256 + threadIdx.x;  // i = n*LATENT + f
    int f = i & (LATENT - 1);
    int n = i >> 7;
    out[i] = __float2half(x[(size_t)f * KCOLS + n]);
}

// ---------------------------------------------------------------------------
// HMMA GEMM (hi-only):  C = A @ B^T,  A fp16 weights, B fp16 activations.
// mode 0: relu + fp16, output TRANSPOSED [n][M].
// mode 1: fp32 raw, output ROW-MAJOR [M][KCOLS] (coalesced for assemble).
// CTA 128x128x32, 256 threads, warp tile 64x32, 3-stage cp.async, 2 CTAs/SM.
// ---------------------------------------------------------------------------
#define BM 128
#define BN 128
#define BK 32
#define GT 256
#define PITCH 80
#define TILE_B (128 * PITCH)      // 10240
#define OFF_AH 0
#define OFF_B  TILE_B
#define STAGE_B (2 * TILE_B)      // 20480
#define NSTAGE 3
#define GEMM_SMEM (128 * 132 * 4) // 67584 (epilogue tile dominates 3*STAGE_B)

__device__ __forceinline__ void load_stage(
    const __half* __restrict__ Ah, const __half* __restrict__ B,
    int Kd, int m0, int n0, int kk, uint32_t stage_sb, int tid)
{
    // 256 rows (Ah 128, B 128), 4 x 16B chunks each = 1024 chunks.
#pragma unroll
    for (int i = 0; i < 4; i++) {
        const int c = tid + i * 256;
        const int row = c >> 2;
        const int cb = (c & 3) * 16;
        const __half* gsrc;
        int grow;
        uint32_t soff;
        if (row < 128) { gsrc = Ah; grow = m0 + row;       soff = OFF_AH + row * PITCH; }
        else           { gsrc = B;  grow = n0 + row - 128; soff = OFF_B  + (row - 128) * PITCH; }
        cp16(stage_sb + soff + cb,
             (const char*)(gsrc + (size_t)grow * Kd + kk) + cb);
    }
}

__global__ __launch_bounds__(GT, 2) void gemm_hmma_kernel(
    const __half* __restrict__ A_hi, const __half* __restrict__ B,
    __half* __restrict__ out_h, float* __restrict__ out_f32,
    int M, int Kd, int mode, int ktps, size_t out_stride)
{
    extern __shared__ __align__(128) char smem[];
    const uint32_t sb = smem_u32(smem);
    const int tid = threadIdx.x;
    const int lane = tid & 31;
    const int wid = tid >> 5;                 // 0..7
    const int warp_m0 = (wid & 1) * 64;
    const int warp_n0 = (wid >> 1) * 32;
    const int m0 = blockIdx.y * BM;
    const int n0 = blockIdx.x * BN;
    const int KT = Kd / BK;
    const int ktb = blockIdx.z * ktps;
    const int L = min(KT - ktb, ktps);
    out_f32 += (size_t)blockIdx.z * out_stride;

    const int a_row = (lane & 7) + ((lane >> 3) & 1) * 8;
    const int a_kb  = (lane >> 4) * 16;
    const int b_row = (lane & 7) + (lane >> 4) * 8;
    const int b_kb  = ((lane >> 3) & 1) * 16;

    float acc[4][4][4];
#pragma unroll
    for (int mt = 0; mt < 4; mt++)
#pragma unroll
        for (int nt = 0; nt < 4; nt++)
#pragma unroll
            for (int i = 0; i < 4; i++) acc[mt][nt][i] = 0.0f;

    load_stage(A_hi, B, Kd, m0, n0, ktb * BK, sb, tid);
    CP_COMMIT();
    load_stage(A_hi, B, Kd, m0, n0, (ktb + 1) * BK, sb + STAGE_B, tid);
    CP_COMMIT();

    for (int kt = 0; kt < L; kt++) {
        asm volatile("cp.async.wait_group 1;" ::: "memory");
        __syncthreads();

        if (kt + 2 < L) {
            load_stage(A_hi, B, Kd, m0, n0, (ktb + kt + 2) * BK,
                       sb + ((kt + 2) % NSTAGE) * STAGE_B, tid);
        }
        CP_COMMIT();

        const uint32_t st = sb + (kt % NSTAGE) * STAGE_B;
#pragma unroll
        for (int ks = 0; ks < 2; ks++) {
            const int kb = ks * 32;
            uint32_t bq[2][4];
#pragma unroll
            for (int g = 0; g < 2; g++) {
                uint32_t rb = st + OFF_B + (warp_n0 + g * 16 + b_row) * PITCH + kb + b_kb;
                ldsm_x4(rb, bq[g]);
            }
#pragma unroll
            for (int mt = 0; mt < 4; mt++) {
                uint32_t ah[4];
                uint32_t ra = st + (warp_m0 + mt * 16 + a_row) * PITCH + kb + a_kb;
                ldsm_x4(ra + OFF_AH, ah);
#pragma unroll
                for (int nt = 0; nt < 4; nt++) {
                    const int g = nt >> 1, p = (nt & 1) * 2;
                    mma_f16(acc[mt][nt], ah, bq[g][p], bq[g][p + 1]);
                }
            }
        }
    }

    // ---------------- epilogue: transpose via SMEM (sC layout [n][m]) ------
    __syncthreads();
    float* sC = (float*)smem;
    const int crow = lane >> 2, ccol = (lane & 3) * 2;
#pragma unroll
    for (int mt = 0; mt < 4; mt++)
#pragma unroll
        for (int nt = 0; nt < 4; nt++) {
            const int m_ = warp_m0 + mt * 16 + crow;
            const int n_ = warp_n0 + nt * 8 + ccol;
            const float* c = acc[mt][nt];
            sC[(size_t)n_ * 132 + m_]           = c[0];
            sC[(size_t)(n_ + 1) * 132 + m_]     = c[1];
            sC[(size_t)n_ * 132 + m_ + 8]       = c[2];
            sC[(size_t)(n_ + 1) * 132 + m_ + 8] = c[3];
        }
    __syncthreads();

    if (mode == 0) {
        // transposed fp16 output [n][M]
        const int r  = tid >> 1;          // n row 0..127
        const int mh = (tid & 1) * 64;    // m half
        const size_t base = (size_t)(n0 + r) * M + m0 + mh;
        const float* srow = &sC[(size_t)r * 132 + mh];
#pragma unroll
        for (int j0 = 0; j0 < 64; j0 += 8) {
            __align__(16) __half h8[8];
#pragma unroll
            for (int j = 0; j < 8; j++)
                h8[j] = __float2half(fmaxf(srow[j0 + j], 0.0f));
            *(uint4*)(out_h + base + j0) = *(const uint4*)h8;
        }
    } else {
        // row-major fp32 output [M][KCOLS]: threads span n (coalesced stores)
        const int n_local = tid & 127;
        const int m_base = (tid >> 7) * 64;
        const float* scol = &sC[(size_t)n_local * 132 + m_base];
        float* gout = out_f32 + (size_t)(m0 + m_base) * KCOLS + n0 + n_local;
#pragma unroll 8
        for (int mm = 0; mm < 64; mm++)
            gout[(size_t)mm * KCOLS] = scol[mm];
    }
}

// ---------------------------------------------------------------------------
// expm (3x3) + output assembly; partials are [M][K] -> coalesced reads.
// ---------------------------------------------------------------------------
__device__ __forceinline__ void mm3(const float* X, const float* Y, float* Z) {
#pragma unroll
    for (int r = 0; r < 3; r++)
#pragma unroll
        for (int c = 0; c < 3; c++)
            Z[3 * r + c] = fmaf(X[3 * r + 0], Y[c],
                           fmaf(X[3 * r + 1], Y[3 + c], X[3 * r + 2] * Y[6 + c]));
}

__device__ void expm3(const float* A, float* E) {
    float n0 = fabsf(A[0]) + fabsf(A[1]) + fabsf(A[2]);
    float n1 = fabsf(A[3]) + fabsf(A[4]) + fabsf(A[5]);
    float n2 = fabsf(A[6]) + fabsf(A[7]) + fabsf(A[8]);
    float nrm = fmaxf(n0, fmaxf(n1, n2));
    int s = 0;
    if (nrm > 0.25f) {
        s = (int)ceilf(log2f(nrm * 4.0f));
        if (s < 0) s = 0;
    }
    float sc = exp2f((float)(-s));
    float B[9], T[9];
#pragma unroll
    for (int i = 0; i < 9; i++) B[i] = A[i] * sc;
#pragma unroll
    for (int i = 0; i < 9; i++) {
        T[i] = B[i];
        E[i] = ((i == 0) | (i == 4) | (i == 8)) ? 1.0f + B[i] : B[i];
    }
#pragma unroll
    for (int j = 2; j <= 10; j++) {
        float Tn[9];
        mm3(T, B, Tn);
        float inv = 1.0f / (float)j;
#pragma unroll
        for (int i = 0; i < 9; i++) { Tn[i] *= inv; E[i] += Tn[i]; T[i] = Tn[i]; }
    }
    for (int q = 0; q < s; q++) {
        float S[9];
        mm3(E, E, S);
#pragma unroll
        for (int i = 0; i < 9; i++) E[i] = S[i];
    }
}

__global__ __launch_bounds__(256) void expm_assemble_kernel(
    const float* __restrict__ omega_part, // 2 x [9n][K]
    const float* __restrict__ trans_part, // 3 x [3n][K]
    float* __restrict__ omega_out,        // (9n, K)
    float* __restrict__ transf,           // (12n, K)
    float* __restrict__ rot,              // (9n, K)
    float* __restrict__ trans_out)        // (3n, K)
{
    const int n = blockIdx.x * 256 + threadIdx.x;
    const int p = blockIdx.y;
    const size_t SO = (size_t)KCOLS * OMEGA_D;
    const size_t ST = (size_t)KCOLS * TRANZ_D;

    float Am[9];
#pragma unroll
    for (int j = 0; j < 9; j++) {
        const size_t off = (size_t)(9 * p + j) * KCOLS + n;
        Am[j] = __ldg(omega_part + off) + __ldg(omega_part + SO + off);
    }

    float E[9];
    expm3(Am, E);

#pragma unroll
    for (int j = 0; j < 9; j++) {
        omega_out[(size_t)(9 * p + j) * KCOLS + n] = Am[j];
        rot[(size_t)(9 * p + j) * KCOLS + n]       = E[j];
        transf[(size_t)(12 * p + j) * KCOLS + n]   = E[j];
    }
#pragma unroll
    for (int c = 0; c < 3; c++) {
        const size_t off = (size_t)(3 * p + c) * KCOLS + n;
        float tv = __ldg(trans_part + off)
                 + __ldg(trans_part + ST + off)
                 + __ldg(trans_part + 2 * ST + off);
        trans_out[(size_t)(3 * p + c) * KCOLS + n]   = tv;
        transf[(size_t)(12 * p + 9 + c) * KCOLS + n] = tv;
    }
}

// ---------------------------------------------------------------------------
// kernel_launch
// ---------------------------------------------------------------------------
extern "C" void kernel_launch(void* const* d_in, const int* in_sizes, int n_in,
                              void* d_out, int out_size)
{
    const float* x = (const float*)d_in[0];
    const float* W[8];
    for (int i = 0; i < 8; i++) W[i] = (const float*)d_in[1 + i];

    const int wsz[8] = {2048 * 128, 2048 * 2048, 2048 * 2048, 1152 * 2048,
                        2048 * 128, 2048 * 2048, 2048 * 2048, 384 * 2048};
    size_t woff[8];
    size_t acc = 0;
    for (int i = 0; i < 8; i++) { woff[i] = acc; acc += wsz[i]; }

    float* out    = (float*)d_out;
    float* omega  = out;
    float* transf = omega  + (size_t)OMEGA_D  * KCOLS;
    float* rot    = transf + (size_t)TRANSF_D * KCOLS;
    float* trans  = rot    + (size_t)OMEGA_D  * KCOLS;

    __half *w_hi, *xt, *a0, *a1;
    float *omega_part, *trans_part;
    cudaGetSymbolAddress((void**)&w_hi, g_w_hi);
    cudaGetSymbolAddress((void**)&xt, g_xt);
    {
        __half* p;
        cudaGetSymbolAddress((void**)&p, g_act);
        a0 = p; a1 = p + (size_t)HIDDEN * KCOLS;
    }
    cudaGetSymbolAddress((void**)&omega_part, g_omega_part);
    cudaGetSymbolAddress((void**)&trans_part, g_trans_part);

    cudaFuncSetAttribute(gemm_hmma_kernel,
                         cudaFuncAttributeMaxDynamicSharedMemorySize, GEMM_SMEM);

    // 1) weight convert + xT convert
    convert_w_kernel<<<(W_STRIDE + 255) / 256, 256>>>(
        W[0], W[1], W[2], W[3], W[4], W[5], W[6], W[7], w_hi);
    split_xT_kernel<<<(KCOLS * LATENT) / 256, 256>>>(x, xt);

    // 2) GEMM chains (all hi-only)
    auto gemm = [&](int wi, const __half* b, __half* oh, float* of,
                    int M, int Kd, int mode, int zsplits, size_t ostride) {
        int KT = Kd / BK;
        int ktps = (KT + zsplits - 1) / zsplits;
        dim3 grid(KCOLS / BN, M / BM, zsplits);
        gemm_hmma_kernel<<<grid, GT, GEMM_SMEM>>>(
            w_hi + woff[wi], b, oh, of, M, Kd, mode, ktps, ostride);
    };

    // omega branch (layer3 split-K x2)
    gemm(0, xt, a0, nullptr, HIDDEN,  LATENT, 0, 1, 0);
    gemm(1, a0, a1, nullptr, HIDDEN,  HIDDEN, 0, 1, 0);
    gemm(2, a1, a0, nullptr, HIDDEN,  HIDDEN, 0, 1, 0);
    gemm(3, a0, nullptr, omega_part, OMEGA_D, HIDDEN, 1, 2,
         (size_t)KCOLS * OMEGA_D);
    // translation branch (layer7 split-K x3)
    gemm(4, xt, a0, nullptr, HIDDEN,  LATENT, 0, 1, 0);
    gemm(5, a0, a1, nullptr, HIDDEN,  HIDDEN, 0, 1, 0);
    gemm(6, a1, a0, nullptr, HIDDEN,  HIDDEN, 0, 1, 0);
    gemm(7, a0, nullptr, trans_part, TRANZ_D, HIDDEN, 1, 3,
         (size_t)KCOLS * TRANZ_D);

    // 3) expm + assembly
    dim3 ge(KCOLS / 256, NPARTS);
    expm_assemble_kernel<<<ge, 256>>>(omega_part, trans_part, omega, transf,
                                      rot, trans);
}

// round 14
// speedup vs baseline: 2.4586x; 1.1576x over previous
#include <cuda_runtime.h>
#include <cuda_fp16.h>
#include <cstdint>

#define LATENT   128
#define HIDDEN   2048
#define NPARTS   128
#define KCOLS    2048
#define OMEGA_D  1152
#define TRANZ_D  384
#define TRANSF_D 1536

// ---------------------------------------------------------------------------
// Scratch (__device__ globals; allocation-guard-safe)
// ---------------------------------------------------------------------------
#define W_TOTAL (2048*128 + 2048*2048 + 2048*2048 + 1152*2048 + \
                 2048*128 + 2048*2048 + 2048*2048 + 384*2048)

__device__ __half g_w_hi[W_TOTAL];
__device__ __half g_act[2][HIDDEN * KCOLS];     // plain fp16 activations
__device__ __half g_xt[KCOLS * LATENT];
__device__ float g_omega_part[2 * (size_t)KCOLS * OMEGA_D];  // [M][K] layout
__device__ float g_trans_part[3 * (size_t)KCOLS * TRANZ_D];  // [M][K] layout

// ---------------------------------------------------------------------------
// PTX helpers (base ISA: ldmatrix / mma.sync / cp.async)
// ---------------------------------------------------------------------------
__device__ __forceinline__ uint32_t smem_u32(const void* p) {
    uint32_t a;
    asm("{ .reg .u64 t; cvta.to.shared.u64 t, %1; cvt.u32.u64 %0, t; }" : "=r"(a) : "l"(p));
    return a;
}
__device__ __forceinline__ void cp16(uint32_t s, const void* g) {
    asm volatile("cp.async.cg.shared.global [%0], [%1], 16;" :: "r"(s), "l"(g) : "memory");
}
#define CP_COMMIT() asm volatile("cp.async.commit_group;" ::: "memory")

__device__ __forceinline__ void ldsm_x4(uint32_t addr, uint32_t* r) {
    asm volatile("ldmatrix.sync.aligned.m8n8.x4.shared.b16 {%0,%1,%2,%3}, [%4];"
                 : "=r"(r[0]), "=r"(r[1]), "=r"(r[2]), "=r"(r[3]) : "r"(addr));
}
__device__ __forceinline__ void mma_f16(float* c, const uint32_t* a,
                                        uint32_t b0, uint32_t b1) {
    asm volatile(
        "mma.sync.aligned.m16n8k16.row.col.f32.f16.f16.f32 "
        "{%0,%1,%2,%3}, {%4,%5,%6,%7}, {%8,%9}, {%0,%1,%2,%3};"
        : "+f"(c[0]), "+f"(c[1]), "+f"(c[2]), "+f"(c[3])
        : "r"(a[0]), "r"(a[1]), "r"(a[2]), "r"(a[3]), "r"(b0), "r"(b1));
}

// ---------------------------------------------------------------------------
// Weight convert: all 8 weights -> hi fp16, one launch, 4-way MLP.
// ---------------------------------------------------------------------------
#define W_CHUNKS 5111808            // total float4 chunks
#define W_STRIDE 1277952            // ceil(W_CHUNKS / 4)

__global__ __launch_bounds__(256) void convert_w_kernel(
    const float* __restrict__ w0, const float* __restrict__ w1,
    const float* __restrict__ w2, const float* __restrict__ w3,
    const float* __restrict__ w4, const float* __restrict__ w5,
    const float* __restrict__ w6, const float* __restrict__ w7,
    __half* __restrict__ hi)
{
    const int cum[8] = {65536, 1114112, 2162688, 2752512,
                        2818048, 3866624, 4915200, 5111808};
    const float* srcs[8] = {w0, w1, w2, w3, w4, w5, w6, w7};
    const int base = blockIdx.x * 256 + threadIdx.x;

    int   idxs[4];
    const float4* gp[4];
    bool  ok[4];
#pragma unroll
    for (int r = 0; r < 4; r++) {
        int idx = base + r * W_STRIDE;
        idxs[r] = idx;
        ok[r] = (idx < W_CHUNKS);
        if (ok[r]) {
            int s = 0;
#pragma unroll
            for (int i = 0; i < 7; i++) s += (idx >= cum[i]);
            int local = idx - (s ? cum[s - 1] : 0);
            gp[r] = (const float4*)srcs[s] + local;
        } else {
            gp[r] = (const float4*)w0;  // dummy
        }
    }
    float4 v[4];
#pragma unroll
    for (int r = 0; r < 4; r++)
        if (ok[r]) v[r] = *gp[r];
#pragma unroll
    for (int r = 0; r < 4; r++) {
        if (!ok[r]) continue;
        float f[4] = {v[r].x, v[r].y, v[r].z, v[r].w};
        __align__(8) __half h[4];
#pragma unroll
        for (int j = 0; j < 4; j++) h[j] = __float2half(f[j]);
        ((uint2*)hi)[idxs[r]] = *(const uint2*)h;
    }
}

// x (LATENT, KCOLS) -> xt (KCOLS, LATENT), plain fp16
__global__ __launch_bounds__(256) void split_xT_kernel(
    const float* __restrict__ x, __half* __restrict__ out)
{
    int i = blockIdx.x * 256 + threadIdx.x;  // i = n*LATENT + f
    int f = i & (LATENT - 1);
    int n = i >> 7;
    out[i] = __float2half(x[(size_t)f * KCOLS + n]);
}

// ---------------------------------------------------------------------------
// HMMA GEMM (hi-only):  C = A @ B^T,  A fp16 weights, B fp16 activations.
// mode 0: relu + fp16, output TRANSPOSED [n][M].
// mode 1: fp32 raw, output ROW-MAJOR [M][KCOLS] (coalesced for assemble).
// CTA 128x128x32, 128 threads (4 warps), warp tile 64x64 (2m x 2n),
// 3-stage cp.async, 2 CTAs/SM.
// ---------------------------------------------------------------------------
#define BM 128
#define BN 128
#define BK 32
#define GT 128
#define PITCH 80
#define TILE_B (128 * PITCH)      // 10240
#define OFF_AH 0
#define OFF_B  TILE_B
#define STAGE_B (2 * TILE_B)      // 20480
#define NSTAGE 3
#define GEMM_SMEM (128 * 132 * 4) // 67584 (epilogue tile dominates 3*STAGE_B)

__device__ __forceinline__ void load_stage(
    const __half* __restrict__ Ah, const __half* __restrict__ B,
    int Kd, int m0, int n0, int kk, uint32_t stage_sb, int tid)
{
    // 256 rows (Ah 128, B 128), 4 x 16B chunks each = 1024 chunks.
#pragma unroll
    for (int i = 0; i < 8; i++) {
        const int c = tid + i * GT;
        const int row = c >> 2;
        const int cb = (c & 3) * 16;
        const __half* gsrc;
        int grow;
        uint32_t soff;
        if (row < 128) { gsrc = Ah; grow = m0 + row;       soff = OFF_AH + row * PITCH; }
        else           { gsrc = B;  grow = n0 + row - 128; soff = OFF_B  + (row - 128) * PITCH; }
        cp16(stage_sb + soff + cb,
             (const char*)(gsrc + (size_t)grow * Kd + kk) + cb);
    }
}

__global__ __launch_bounds__(GT, 2) void gemm_hmma_kernel(
    const __half* __restrict__ A_hi, const __half* __restrict__ B,
    __half* __restrict__ out_h, float* __restrict__ out_f32,
    int M, int Kd, int mode, int ktps, size_t out_stride)
{
    extern __shared__ __align__(128) char smem[];
    const uint32_t sb = smem_u32(smem);
    const int tid = threadIdx.x;
    const int lane = tid & 31;
    const int wid = tid >> 5;                 // 0..3
    const int warp_m0 = (wid & 1) * 64;
    const int warp_n0 = (wid >> 1) * 64;
    const int m0 = blockIdx.y * BM;
    const int n0 = blockIdx.x * BN;
    const int KT = Kd / BK;
    const int ktb = blockIdx.z * ktps;
    const int L = min(KT - ktb, ktps);
    out_f32 += (size_t)blockIdx.z * out_stride;

    const int a_row = (lane & 7) + ((lane >> 3) & 1) * 8;
    const int a_kb  = (lane >> 4) * 16;
    const int b_row = (lane & 7) + (lane >> 4) * 8;
    const int b_kb  = ((lane >> 3) & 1) * 16;

    float acc[4][8][4];   // mt (m 4x16) x nt (n 8x8) x 4
#pragma unroll
    for (int mt = 0; mt < 4; mt++)
#pragma unroll
        for (int nt = 0; nt < 8; nt++)
#pragma unroll
            for (int i = 0; i < 4; i++) acc[mt][nt][i] = 0.0f;

    load_stage(A_hi, B, Kd, m0, n0, ktb * BK, sb, tid);
    CP_COMMIT();
    load_stage(A_hi, B, Kd, m0, n0, (ktb + 1) * BK, sb + STAGE_B, tid);
    CP_COMMIT();

    for (int kt = 0; kt < L; kt++) {
        asm volatile("cp.async.wait_group 1;" ::: "memory");
        __syncthreads();

        if (kt + 2 < L) {
            load_stage(A_hi, B, Kd, m0, n0, (ktb + kt + 2) * BK,
                       sb + ((kt + 2) % NSTAGE) * STAGE_B, tid);
        }
        CP_COMMIT();

        const uint32_t st = sb + (kt % NSTAGE) * STAGE_B;
#pragma unroll
        for (int ks = 0; ks < 2; ks++) {
            const int kb = ks * 32;
            uint32_t bq[4][4];
#pragma unroll
            for (int g = 0; g < 4; g++) {
                uint32_t rb = st + OFF_B + (warp_n0 + g * 16 + b_row) * PITCH + kb + b_kb;
                ldsm_x4(rb, bq[g]);
            }
#pragma unroll
            for (int mt = 0; mt < 4; mt++) {
                uint32_t ah[4];
                uint32_t ra = st + (warp_m0 + mt * 16 + a_row) * PITCH + kb + a_kb;
                ldsm_x4(ra + OFF_AH, ah);
#pragma unroll
                for (int nt = 0; nt < 8; nt++) {
                    const int g = nt >> 1, p = (nt & 1) * 2;
                    mma_f16(acc[mt][nt], ah, bq[g][p], bq[g][p + 1]);
                }
            }
        }
    }

    // ---------------- epilogue: transpose via SMEM (sC layout [n][m]) ------
    __syncthreads();
    float* sC = (float*)smem;
    const int crow = lane >> 2, ccol = (lane & 3) * 2;
#pragma unroll
    for (int mt = 0; mt < 4; mt++)
#pragma unroll
        for (int nt = 0; nt < 8; nt++) {
            const int m_ = warp_m0 + mt * 16 + crow;
            const int n_ = warp_n0 + nt * 8 + ccol;
            const float* c = acc[mt][nt];
            sC[(size_t)n_ * 132 + m_]           = c[0];
            sC[(size_t)(n_ + 1) * 132 + m_]     = c[1];
            sC[(size_t)n_ * 132 + m_ + 8]       = c[2];
            sC[(size_t)(n_ + 1) * 132 + m_ + 8] = c[3];
        }
    __syncthreads();

    if (mode == 0) {
        // transposed fp16 output [n][M]: each thread one n-row, 128 m values
        const int r = tid;                // n row 0..127
        const size_t base = (size_t)(n0 + r) * M + m0;
        const float* srow = &sC[(size_t)r * 132];
#pragma unroll
        for (int j0 = 0; j0 < 128; j0 += 8) {
            __align__(16) __half h8[8];
#pragma unroll
            for (int j = 0; j < 8; j++)
                h8[j] = __float2half(fmaxf(srow[j0 + j], 0.0f));
            *(uint4*)(out_h + base + j0) = *(const uint4*)h8;
        }
    } else {
        // row-major fp32 output [M][KCOLS]: threads span n (coalesced stores)
        const int n_local = tid;
        const float* scol = &sC[(size_t)n_local * 132];
        float* gout = out_f32 + (size_t)m0 * KCOLS + n0 + n_local;
#pragma unroll 8
        for (int mm = 0; mm < 128; mm++)
            gout[(size_t)mm * KCOLS] = scol[mm];
    }
}

// ---------------------------------------------------------------------------
// expm (3x3) + output assembly; partials are [M][K] -> coalesced reads.
// ---------------------------------------------------------------------------
__device__ __forceinline__ void mm3(const float* X, const float* Y, float* Z) {
#pragma unroll
    for (int r = 0; r < 3; r++)
#pragma unroll
        for (int c = 0; c < 3; c++)
            Z[3 * r + c] = fmaf(X[3 * r + 0], Y[c],
                           fmaf(X[3 * r + 1], Y[3 + c], X[3 * r + 2] * Y[6 + c]));
}

__device__ void expm3(const float* A, float* E) {
    float n0 = fabsf(A[0]) + fabsf(A[1]) + fabsf(A[2]);
    float n1 = fabsf(A[3]) + fabsf(A[4]) + fabsf(A[5]);
    float n2 = fabsf(A[6]) + fabsf(A[7]) + fabsf(A[8]);
    float nrm = fmaxf(n0, fmaxf(n1, n2));
    int s = 0;
    if (nrm > 0.25f) {
        s = (int)ceilf(log2f(nrm * 4.0f));
        if (s < 0) s = 0;
    }
    float sc = exp2f((float)(-s));
    float B[9], T[9];
#pragma unroll
    for (int i = 0; i < 9; i++) B[i] = A[i] * sc;
#pragma unroll
    for (int i = 0; i < 9; i++) {
        T[i] = B[i];
        E[i] = ((i == 0) | (i == 4) | (i == 8)) ? 1.0f + B[i] : B[i];
    }
#pragma unroll
    for (int j = 2; j <= 10; j++) {
        float Tn[9];
        mm3(T, B, Tn);
        float inv = 1.0f / (float)j;
#pragma unroll
        for (int i = 0; i < 9; i++) { Tn[i] *= inv; E[i] += Tn[i]; T[i] = Tn[i]; }
    }
    for (int q = 0; q < s; q++) {
        float S[9];
        mm3(E, E, S);
#pragma unroll
        for (int i = 0; i < 9; i++) E[i] = S[i];
    }
}

__global__ __launch_bounds__(256) void expm_assemble_kernel(
    const float* __restrict__ omega_part, // 2 x [9n][K]
    const float* __restrict__ trans_part, // 3 x [3n][K]
    float* __restrict__ omega_out,        // (9n, K)
    float* __restrict__ transf,           // (12n, K)
    float* __restrict__ rot,              // (9n, K)
    float* __restrict__ trans_out)        // (3n, K)
{
    const int n = blockIdx.x * 256 + threadIdx.x;
    const int p = blockIdx.y;
    const size_t SO = (size_t)KCOLS * OMEGA_D;
    const size_t ST = (size_t)KCOLS * TRANZ_D;

    float Am[9];
#pragma unroll
    for (int j = 0; j < 9; j++) {
        const size_t off = (size_t)(9 * p + j) * KCOLS + n;
        Am[j] = __ldg(omega_part + off) + __ldg(omega_part + SO + off);
    }

    float E[9];
    expm3(Am, E);

#pragma unroll
    for (int j = 0; j < 9; j++) {
        omega_out[(size_t)(9 * p + j) * KCOLS + n] = Am[j];
        rot[(size_t)(9 * p + j) * KCOLS + n]       = E[j];
        transf[(size_t)(12 * p + j) * KCOLS + n]   = E[j];
    }
#pragma unroll
    for (int c = 0; c < 3; c++) {
        const size_t off = (size_t)(3 * p + c) * KCOLS + n;
        float tv = __ldg(trans_part + off)
                 + __ldg(trans_part + ST + off)
                 + __ldg(trans_part + 2 * ST + off);
        trans_out[(size_t)(3 * p + c) * KCOLS + n]   = tv;
        transf[(size_t)(12 * p + 9 + c) * KCOLS + n] = tv;
    }
}

// ---------------------------------------------------------------------------
// kernel_launch
// ---------------------------------------------------------------------------
extern "C" void kernel_launch(void* const* d_in, const int* in_sizes, int n_in,
                              void* d_out, int out_size)
{
    const float* x = (const float*)d_in[0];
    const float* W[8];
    for (int i = 0; i < 8; i++) W[i] = (const float*)d_in[1 + i];

    const int wsz[8] = {2048 * 128, 2048 * 2048, 2048 * 2048, 1152 * 2048,
                        2048 * 128, 2048 * 2048, 2048 * 2048, 384 * 2048};
    size_t woff[8];
    size_t acc = 0;
    for (int i = 0; i < 8; i++) { woff[i] = acc; acc += wsz[i]; }

    float* out    = (float*)d_out;
    float* omega  = out;
    float* transf = omega  + (size_t)OMEGA_D  * KCOLS;
    float* rot    = transf + (size_t)TRANSF_D * KCOLS;
    float* trans  = rot    + (size_t)OMEGA_D  * KCOLS;

    __half *w_hi, *xt, *a0, *a1;
    float *omega_part, *trans_part;
    cudaGetSymbolAddress((void**)&w_hi, g_w_hi);
    cudaGetSymbolAddress((void**)&xt, g_xt);
    {
        __half* p;
        cudaGetSymbolAddress((void**)&p, g_act);
        a0 = p; a1 = p + (size_t)HIDDEN * KCOLS;
    }
    cudaGetSymbolAddress((void**)&omega_part, g_omega_part);
    cudaGetSymbolAddress((void**)&trans_part, g_trans_part);

    cudaFuncSetAttribute(gemm_hmma_kernel,
                         cudaFuncAttributeMaxDynamicSharedMemorySize, GEMM_SMEM);

    // 1) weight convert + xT convert
    convert_w_kernel<<<(W_STRIDE + 255) / 256, 256>>>(
        W[0], W[1], W[2], W[3], W[4], W[5], W[6], W[7], w_hi);
    split_xT_kernel<<<(KCOLS * LATENT) / 256, 256>>>(x, xt);

    // 2) GEMM chains (all hi-only)
    auto gemm = [&](int wi, const __half* b, __half* oh, float* of,
                    int M, int Kd, int mode, int zsplits, size_t ostride) {
        int KT = Kd / BK;
        int ktps = (KT + zsplits - 1) / zsplits;
        dim3 grid(KCOLS / BN, M / BM, zsplits);
        gemm_hmma_kernel<<<grid, GT, GEMM_SMEM>>>(
            w_hi + woff[wi], b, oh, of, M, Kd, mode, ktps, ostride);
    };

    // omega branch (layer3 split-K x2)
    gemm(0, xt, a0, nullptr, HIDDEN,  LATENT, 0, 1, 0);
    gemm(1, a0, a1, nullptr, HIDDEN,  HIDDEN, 0, 1, 0);
    gemm(2, a1, a0, nullptr, HIDDEN,  HIDDEN, 0, 1, 0);
    gemm(3, a0, nullptr, omega_part, OMEGA_D, HIDDEN, 1, 2,
         (size_t)KCOLS * OMEGA_D);
    // translation branch (layer7 split-K x3)
    gemm(4, xt, a0, nullptr, HIDDEN,  LATENT, 0, 1, 0);
    gemm(5, a0, a1, nullptr, HIDDEN,  HIDDEN, 0, 1, 0);
    gemm(6, a1, a0, nullptr, HIDDEN,  HIDDEN, 0, 1, 0);
    gemm(7, a0, nullptr, trans_part, TRANZ_D, HIDDEN, 1, 3,
         (size_t)KCOLS * TRANZ_D);

    // 3) expm + assembly
    dim3 ge(KCOLS / 256, NPARTS);
    expm_assemble_kernel<<<ge, 256>>>(omega_part, trans_part, omega, transf,
                                      rot, trans);
}